// round 10
// baseline (speedup 1.0000x reference)
#include <cuda_runtime.h>
#include <cuda_fp16.h>
#include <math.h>
#include <stdint.h>

#define BATCH   512
#define STEPS   128
#define TSTEPS  255          // 127 history + 128 action
#define DIN     256
#define UDIM    256
#define G4      1024         // 4*UDIM
#define RROWS   4            // batch rows per recurrence CTA
#define RCTAS   (BATCH / RROWS)                 // 128

// Scratch (static device allocations — no cudaMalloc anywhere)
__device__ float  g_state[BATCH * UDIM];
__device__ float  g_h[BATCH * UDIM];
__device__ float  g_G[(size_t)TSTEPS * BATCH * G4];   // 535 MB: x@Wk + bl, [t][b][4U]
__device__ uint4  g_Whp[128 * 256];   // fp16 Wrk: k-pair x n -> {(wi,wf),(wg,wo)}k, {..}k+1

// ---------------------------------------------------------------------------
// f32x2 packed-FMA helpers (sm_103a FFMA2 — only reachable via PTX)
// ---------------------------------------------------------------------------
union F2U { float2 f; unsigned long long u; };
union F4U { float4 f; ulonglong2 u; };

__device__ __forceinline__ void fma2(unsigned long long& d,
                                     unsigned long long a,
                                     unsigned long long b)
{
    asm("fma.rn.f32x2 %0, %1, %2, %0;" : "+l"(d) : "l"(a), "l"(b));
}
__device__ __forceinline__ unsigned long long dup2(float x)
{
    F2U t; t.f = make_float2(x, x); return t.u;
}
__device__ __forceinline__ float tanha(float x)
{
    float y; asm("tanh.approx.f32 %0, %1;" : "=f"(y) : "f"(x)); return y;
}
__device__ __forceinline__ float sigm(float x)
{
    return fmaf(0.5f, tanha(0.5f * x), 0.5f);
}
__device__ __forceinline__ unsigned long long h2f2(uint32_t h2bits)
{
    __half2 h = *(__half2*)&h2bits;
    F2U t; t.f = __half22float2(h);
    return t.u;
}

// ---------------------------------------------------------------------------
// K0: reformat Wrk [256,1024] -> fp16 k-pair layout:
// g_Whp[kk*256 + n] = { h2(wi,wf)@k=2kk, h2(wg,wo)@k=2kk, h2(wi,wf)@k=2kk+1, h2(wg,wo)@k=2kk+1 }
// ---------------------------------------------------------------------------
__global__ void reformat_wrk(const float* __restrict__ Wrk)
{
    const int idx = blockIdx.x * 256 + threadIdx.x;   // 32768
    const int kk = idx >> 8, n = idx & 255;
    const float* w0 = Wrk + (2*kk)     * G4 + n;
    const float* w1 = Wrk + (2*kk + 1) * G4 + n;
    __half2 a = __floats2half2_rn(w0[0],   w0[256]);
    __half2 b = __floats2half2_rn(w0[512], w0[768]);
    __half2 c = __floats2half2_rn(w1[0],   w1[256]);
    __half2 d = __floats2half2_rn(w1[512], w1[768]);
    uint4 out;
    out.x = *(uint32_t*)&a; out.y = *(uint32_t*)&b;
    out.z = *(uint32_t*)&c; out.w = *(uint32_t*)&d;
    g_Whp[idx] = out;
}

// ---------------------------------------------------------------------------
// K1: preamble — ms/rs/re/im + combine -> state [512,256]
// ---------------------------------------------------------------------------
__global__ void __launch_bounds__(256) preamble_kernel(
    const float* __restrict__ motion, const float* __restrict__ robot,
    const float* __restrict__ osr,    const float* __restrict__ osi,
    const float* __restrict__ orr_,   const float* __restrict__ ori_,
    const float* __restrict__ Wm, const float* __restrict__ bm,
    const float* __restrict__ Wr, const float* __restrict__ br,
    const float* __restrict__ Wre, const float* __restrict__ bre,
    const float* __restrict__ Wim, const float* __restrict__ bim,
    const float* __restrict__ Wc,  const float* __restrict__ bc)
{
    __shared__ float comb[768];
    const int row = blockIdx.x;
    const int n   = threadIdx.x;

    float s = bm[n];
    #pragma unroll 8
    for (int k = 0; k < 64; k++) s += motion[row*64 + k] * Wm[k*256 + n];
    comb[n] = fmaxf(s, 0.f);

    s = br[n];
    #pragma unroll 8
    for (int k = 0; k < 128; k++) s += robot[row*128 + k] * Wr[k*256 + n];
    comb[256 + n] = fmaxf(s, 0.f);

    if (n < 128) {
        float s3 = bre[n];
        #pragma unroll 8
        for (int k = 0; k < 64; k++) s3 += osr [row*64 + k] * Wre[k*128 + n];
        #pragma unroll 8
        for (int k = 0; k < 64; k++) s3 += orr_[row*64 + k] * Wre[(64+k)*128 + n];
        comb[512 + n] = fmaxf(s3, 0.f);
    } else {
        const int m = n - 128;
        float s4 = bim[m];
        #pragma unroll 8
        for (int k = 0; k < 64; k++) s4 += osi [row*64 + k] * Wim[k*128 + m];
        #pragma unroll 8
        for (int k = 0; k < 64; k++) s4 += ori_[row*64 + k] * Wim[(64+k)*128 + m];
        comb[640 + m] = fmaxf(s4, 0.f);
    }
    __syncthreads();

    float s5 = bc[n];
    #pragma unroll 8
    for (int k = 0; k < 768; k++) s5 += comb[k] * Wc[k*256 + n];
    g_state[row*256 + n] = fmaxf(s5, 0.f);
}

// ---------------------------------------------------------------------------
// K2: G = x @ Wk + bl.  M=130560, K=256, N=1024.
// 128x128 tile, BK=16, 256 threads, 8x8 microtile, FFMA2, reg-prefetch.
// ---------------------------------------------------------------------------
__global__ void __launch_bounds__(256, 1) xwk_kernel(
    const float* __restrict__ hist, const float* __restrict__ act,
    const float* __restrict__ Wk,   const float* __restrict__ bl)
{
    __shared__ float As[16][132];
    __shared__ float Bs[16][128];

    const int tid = threadIdx.x;
    const int tx  = tid & 15, ty = tid >> 4;
    const int bm0 = blockIdx.y * 128;
    const int bn0 = blockIdx.x * 128;

    const int ra = tid >> 2;
    const int kc = (tid & 3) * 4;
    const int mA0 = bm0 + ra, mA1 = bm0 + ra + 64;
    const int tA0 = mA0 >> 9, bA0 = mA0 & 511;
    const int tA1 = mA1 >> 9, bA1 = mA1 & 511;
    const float* arow0 = (tA0 < 127)
        ? (hist + ((size_t)bA0 * STEPS + tA0) * DIN)
        : (act  + ((size_t)bA0 * STEPS + (tA0 - 127)) * DIN);
    const float* arow1 = (tA1 < 127)
        ? (hist + ((size_t)bA1 * STEPS + tA1) * DIN)
        : (act  + ((size_t)bA1 * STEPS + (tA1 - 127)) * DIN);

    const int kb = tid >> 4;
    const int nb = (tid & 15) * 4;
    const float* bsrc = Wk + (size_t)kb * G4 + bn0 + nb;

    unsigned long long acc[8][4];
    #pragma unroll
    for (int i = 0; i < 8; i++)
        #pragma unroll
        for (int j = 0; j < 4; j++) acc[i][j] = 0ull;

    float4 a0 = *(const float4*)(arow0 + kc);
    float4 a1 = *(const float4*)(arow1 + kc);
    float4 b0 = *(const float4*)(bsrc);
    float4 b1 = *(const float4*)(bsrc + 64);

    for (int k0 = 0; k0 < 256; k0 += 16) {
        __syncthreads();
        As[kc+0][ra] = a0.x; As[kc+1][ra] = a0.y; As[kc+2][ra] = a0.z; As[kc+3][ra] = a0.w;
        As[kc+0][ra+64] = a1.x; As[kc+1][ra+64] = a1.y; As[kc+2][ra+64] = a1.z; As[kc+3][ra+64] = a1.w;
        *(float4*)&Bs[kb][nb]      = b0;
        *(float4*)&Bs[kb][nb + 64] = b1;
        __syncthreads();

        if (k0 + 16 < 256) {
            a0 = *(const float4*)(arow0 + k0 + 16 + kc);
            a1 = *(const float4*)(arow1 + k0 + 16 + kc);
            b0 = *(const float4*)(bsrc + (size_t)(k0 + 16) * G4);
            b1 = *(const float4*)(bsrc + (size_t)(k0 + 16) * G4 + 64);
        }

        #pragma unroll
        for (int k = 0; k < 16; k++) {
            float4 av0 = *(const float4*)&As[k][ty*8];
            float4 av1 = *(const float4*)&As[k][ty*8 + 4];
            F4U bv0, bv1;
            bv0.f = *(const float4*)&Bs[k][tx*8];
            bv1.f = *(const float4*)&Bs[k][tx*8 + 4];
            unsigned long long bp[4] = { bv0.u.x, bv0.u.y, bv1.u.x, bv1.u.y };
            float afl[8] = { av0.x, av0.y, av0.z, av0.w, av1.x, av1.y, av1.z, av1.w };
            #pragma unroll
            for (int i = 0; i < 8; i++) {
                unsigned long long ad = dup2(afl[i]);
                #pragma unroll
                for (int j = 0; j < 4; j++) fma2(acc[i][j], ad, bp[j]);
            }
        }
    }

    float blv[8];
    #pragma unroll
    for (int j = 0; j < 8; j++) blv[j] = bl[bn0 + tx*8 + j];

    #pragma unroll
    for (int i = 0; i < 8; i++) {
        const int m = bm0 + ty*8 + i;
        float v[8];
        #pragma unroll
        for (int j = 0; j < 4; j++) {
            F2U e; e.u = acc[i][j];
            v[j*2]   = e.f.x + blv[j*2];
            v[j*2+1] = e.f.y + blv[j*2+1];
        }
        float* dst = g_G + (size_t)m * G4 + bn0 + tx*8;
        *(float4*)dst       = make_float4(v[0], v[1], v[2], v[3]);
        *(float4*)(dst + 4) = make_float4(v[4], v[5], v[6], v[7]);
    }
}

// ---------------------------------------------------------------------------
// K3: persistent LSTM recurrence. 128 CTAs x 4 batch rows, 512 threads.
// K-split: warps 0-7 handle k in [0,128), warps 8-15 handle k in [128,256).
// Weight stream in fp16 (half L2 traffic), converted to fp32 in-register,
// FFMA2 math. Partials reduced through smem each step. No cross-CTA sync.
// ---------------------------------------------------------------------------
__global__ void __launch_bounds__(512, 1) recur_kernel()
{
    __shared__ float2 hs2[RROWS][256];        // 8 KB, h duplicated
    __shared__ float4 part[RROWS][256];       // 16 KB, (if.x,if.y,go.x,go.y) partials

    const int tid  = threadIdx.x;
    const int n    = tid & 255;               // gate feature
    const int half = tid >> 8;                // k half: 0 or 1
    const int r0   = blockIdx.x * RROWS;

    float c[RROWS];
    if (half == 0) {
        #pragma unroll
        for (int r = 0; r < RROWS; r++) {
            c[r] = g_state[(r0 + r) * 256 + n];
            hs2[r][n] = make_float2(c[r], c[r]);
        }
    }
    __syncthreads();

    // k-pair pointer: half h owns k-pairs [64h, 64h+64)
    const uint4* wp = g_Whp + (size_t)(half * 64) * 256 + n;
    const int kbase = half * 128;

    for (int t = 0; t < TSTEPS; t++) {
        // hoist G loads (half 0 only) — they land under the k-loop
        float gz[RROWS][4];
        if (half == 0) {
            #pragma unroll
            for (int r = 0; r < RROWS; r++) {
                const float* Gp = g_G + ((size_t)t * BATCH + r0 + r) * G4 + n;
                gz[r][0] = Gp[0];   gz[r][1] = Gp[256];
                gz[r][2] = Gp[512]; gz[r][3] = Gp[768];
            }
        }

        unsigned long long accif[RROWS], accgo[RROWS];
        #pragma unroll
        for (int r = 0; r < RROWS; r++) { accif[r] = 0ull; accgo[r] = 0ull; }

        #pragma unroll 4
        for (int kp = 0; kp < 64; kp++) {
            const uint4 w = wp[(size_t)kp * 256];
            const unsigned long long wif0 = h2f2(w.x);
            const unsigned long long wgo0 = h2f2(w.y);
            const unsigned long long wif1 = h2f2(w.z);
            const unsigned long long wgo1 = h2f2(w.w);
            #pragma unroll
            for (int r = 0; r < RROWS; r++) {
                F4U hh; hh.f = *(const float4*)&hs2[r][kbase + 2*kp];
                fma2(accif[r], wif0, hh.u.x);
                fma2(accgo[r], wgo0, hh.u.x);
                fma2(accif[r], wif1, hh.u.y);
                fma2(accgo[r], wgo1, hh.u.y);
            }
        }

        if (half == 1) {
            #pragma unroll
            for (int r = 0; r < RROWS; r++) {
                F4U p; p.u.x = accif[r]; p.u.y = accgo[r];
                part[r][n] = p.f;
            }
        }
        __syncthreads();   // partials visible; all hs2 reads complete

        if (half == 0) {
            #pragma unroll
            for (int r = 0; r < RROWS; r++) {
                F4U p; p.f = part[r][n];
                F2U eif, ego; eif.u = accif[r]; ego.u = accgo[r];
                const float zi = eif.f.x + p.f.x + gz[r][0];
                const float zf = eif.f.y + p.f.y + gz[r][1];
                const float zg = ego.f.x + p.f.z + gz[r][2];
                const float zo = ego.f.y + p.f.w + gz[r][3];
                const float ig = sigm(zi);
                const float fg = sigm(zf);
                const float gg = tanha(zg);
                const float og = sigm(zo);
                c[r] = fg * c[r] + ig * gg;
                const float h = og * tanha(c[r]);
                hs2[r][n] = make_float2(h, h);
            }
        }
        __syncthreads();   // new h (and freed part) visible to all
    }

    if (half == 0) {
        #pragma unroll
        for (int r = 0; r < RROWS; r++)
            g_h[(r0 + r) * 256 + n] = hs2[r][n].x;
    }
}

// ---------------------------------------------------------------------------
// K4: out = relu(h @ Wo + bo), [512,1]. One warp per batch row.
// ---------------------------------------------------------------------------
__global__ void out_kernel(const float* __restrict__ Wo,
                           const float* __restrict__ bo,
                           float* __restrict__ out)
{
    const int b = blockIdx.x;
    const int lane = threadIdx.x;
    float s = 0.f;
    #pragma unroll
    for (int k = lane; k < 256; k += 32) s += g_h[b*256 + k] * Wo[k];
    #pragma unroll
    for (int off = 16; off; off >>= 1) s += __shfl_down_sync(0xffffffffu, s, off);
    if (lane == 0) out[b] = fmaxf(s + bo[0], 0.f);
}

// ---------------------------------------------------------------------------
extern "C" void kernel_launch(void* const* d_in, const int* in_sizes, int n_in,
                              void* d_out, int out_size)
{
    const float* motion = (const float*)d_in[0];
    const float* robot  = (const float*)d_in[1];
    const float* osr    = (const float*)d_in[2];
    const float* osi    = (const float*)d_in[3];
    const float* hist   = (const float*)d_in[4];
    const float* act    = (const float*)d_in[5];
    const float* orr_   = (const float*)d_in[6];
    const float* ori_   = (const float*)d_in[7];
    const float* Wm  = (const float*)d_in[8];
    const float* bm  = (const float*)d_in[9];
    const float* Wr  = (const float*)d_in[10];
    const float* br  = (const float*)d_in[11];
    const float* Wre = (const float*)d_in[12];
    const float* bre = (const float*)d_in[13];
    const float* Wim = (const float*)d_in[14];
    const float* bim = (const float*)d_in[15];
    const float* Wc  = (const float*)d_in[16];
    const float* bc  = (const float*)d_in[17];
    const float* Wk  = (const float*)d_in[18];
    const float* Wrk = (const float*)d_in[19];
    const float* bl  = (const float*)d_in[20];
    const float* Wo  = (const float*)d_in[21];
    const float* bo  = (const float*)d_in[22];
    float* out = (float*)d_out;

    reformat_wrk<<<128, 256>>>(Wrk);

    preamble_kernel<<<BATCH, 256>>>(motion, robot, osr, osi, orr_, ori_,
                                    Wm, bm, Wr, br, Wre, bre, Wim, bim, Wc, bc);

    dim3 g2(G4 / 128, (TSTEPS * BATCH) / 128);   // (8, 1020)
    xwk_kernel<<<g2, 256>>>(hist, act, Wk, bl);

    recur_kernel<<<RCTAS, 512>>>();

    out_kernel<<<BATCH, 32>>>(Wo, bo, out);
}

// round 13
// speedup vs baseline: 1.4294x; 1.4294x over previous
#include <cuda_runtime.h>
#include <cuda_fp16.h>
#include <math.h>
#include <stdint.h>

#define BATCH   512
#define STEPS   128
#define TSTEPS  255          // 127 history + 128 action
#define DIN     256
#define UDIM    256
#define G4      1024         // 4*UDIM
#define RROWS   4            // batch rows per recurrence CTA
#define RCTAS   (BATCH / RROWS)                 // 128

// Scratch (static device allocations — no cudaMalloc anywhere)
__device__ float  g_state[BATCH * UDIM];
__device__ float  g_h[BATCH * UDIM];
__device__ float  g_G[(size_t)TSTEPS * BATCH * G4];   // x@Wk + bl, [t][b][4U]
__device__ uint4  g_Whp[128 * 256];   // fp16 Wrk k-pair layout (recurrence)
__device__ __half g_WkT[1024 * 256];  // fp16 Wk transposed: [n][k] (k contiguous)

// ---------------------------------------------------------------------------
// helpers
// ---------------------------------------------------------------------------
union F2U { float2 f; unsigned long long u; };
union F4U { float4 f; ulonglong2 u; };

__device__ __forceinline__ void fma2(unsigned long long& d,
                                     unsigned long long a,
                                     unsigned long long b)
{
    asm("fma.rn.f32x2 %0, %1, %2, %0;" : "+l"(d) : "l"(a), "l"(b));
}
__device__ __forceinline__ float tanha(float x)
{
    float y; asm("tanh.approx.f32 %0, %1;" : "=f"(y) : "f"(x)); return y;
}
__device__ __forceinline__ float sigm(float x)
{
    return fmaf(0.5f, tanha(0.5f * x), 0.5f);
}
__device__ __forceinline__ unsigned long long h2f2(uint32_t h2bits)
{
    __half2 h = *(__half2*)&h2bits;
    F2U t; t.f = __half22float2(h);
    return t.u;
}
__device__ __forceinline__ uint32_t smem_u32(const void* p)
{
    uint32_t a;
    asm("{ .reg .u64 t; cvta.to.shared.u64 t, %1; cvt.u32.u64 %0, t; }"
        : "=r"(a) : "l"(p));
    return a;
}
__device__ __forceinline__ void ldsm4(uint32_t& r0, uint32_t& r1,
                                      uint32_t& r2, uint32_t& r3, uint32_t a)
{
    asm volatile("ldmatrix.sync.aligned.m8n8.x4.shared.b16 {%0,%1,%2,%3}, [%4];"
                 : "=r"(r0), "=r"(r1), "=r"(r2), "=r"(r3) : "r"(a));
}
__device__ __forceinline__ void mma16816(float* c, const uint32_t* a,
                                         uint32_t b0, uint32_t b1)
{
    asm volatile(
        "mma.sync.aligned.m16n8k16.row.col.f32.f16.f16.f32 "
        "{%0,%1,%2,%3}, {%4,%5,%6,%7}, {%8,%9}, {%0,%1,%2,%3};"
        : "+f"(c[0]), "+f"(c[1]), "+f"(c[2]), "+f"(c[3])
        : "r"(a[0]), "r"(a[1]), "r"(a[2]), "r"(a[3]), "r"(b0), "r"(b1));
}

// ---------------------------------------------------------------------------
// K0a: reformat Wrk -> fp16 k-pair layout (recurrence)
// ---------------------------------------------------------------------------
__global__ void reformat_wrk(const float* __restrict__ Wrk)
{
    const int idx = blockIdx.x * 256 + threadIdx.x;   // 32768
    const int kk = idx >> 8, n = idx & 255;
    const float* w0 = Wrk + (2*kk)     * G4 + n;
    const float* w1 = Wrk + (2*kk + 1) * G4 + n;
    __half2 a = __floats2half2_rn(w0[0],   w0[256]);
    __half2 b = __floats2half2_rn(w0[512], w0[768]);
    __half2 c = __floats2half2_rn(w1[0],   w1[256]);
    __half2 d = __floats2half2_rn(w1[512], w1[768]);
    uint4 out;
    out.x = *(uint32_t*)&a; out.y = *(uint32_t*)&b;
    out.z = *(uint32_t*)&c; out.w = *(uint32_t*)&d;
    g_Whp[idx] = out;
}

// ---------------------------------------------------------------------------
// K0b: Wk [256,1024] -> fp16 transposed [1024,256] (B operand, col-major k)
// ---------------------------------------------------------------------------
__global__ void reformat_wk(const float* __restrict__ Wk)
{
    const int n = blockIdx.x;            // 1024
    const int k = threadIdx.x;           // 256
    g_WkT[n * 256 + k] = __float2half_rn(Wk[(size_t)k * G4 + n]);
}

// ---------------------------------------------------------------------------
// K1: preamble — ms/rs/re/im + combine -> state [512,256]
// ---------------------------------------------------------------------------
__global__ void __launch_bounds__(256) preamble_kernel(
    const float* __restrict__ motion, const float* __restrict__ robot,
    const float* __restrict__ osr,    const float* __restrict__ osi,
    const float* __restrict__ orr_,   const float* __restrict__ ori_,
    const float* __restrict__ Wm, const float* __restrict__ bm,
    const float* __restrict__ Wr, const float* __restrict__ br,
    const float* __restrict__ Wre, const float* __restrict__ bre,
    const float* __restrict__ Wim, const float* __restrict__ bim,
    const float* __restrict__ Wc,  const float* __restrict__ bc)
{
    __shared__ float comb[768];
    const int row = blockIdx.x;
    const int n   = threadIdx.x;

    float s = bm[n];
    #pragma unroll 8
    for (int k = 0; k < 64; k++) s += motion[row*64 + k] * Wm[k*256 + n];
    comb[n] = fmaxf(s, 0.f);

    s = br[n];
    #pragma unroll 8
    for (int k = 0; k < 128; k++) s += robot[row*128 + k] * Wr[k*256 + n];
    comb[256 + n] = fmaxf(s, 0.f);

    if (n < 128) {
        float s3 = bre[n];
        #pragma unroll 8
        for (int k = 0; k < 64; k++) s3 += osr [row*64 + k] * Wre[k*128 + n];
        #pragma unroll 8
        for (int k = 0; k < 64; k++) s3 += orr_[row*64 + k] * Wre[(64+k)*128 + n];
        comb[512 + n] = fmaxf(s3, 0.f);
    } else {
        const int m = n - 128;
        float s4 = bim[m];
        #pragma unroll 8
        for (int k = 0; k < 64; k++) s4 += osi [row*64 + k] * Wim[k*128 + m];
        #pragma unroll 8
        for (int k = 0; k < 64; k++) s4 += ori_[row*64 + k] * Wim[(64+k)*128 + m];
        comb[640 + m] = fmaxf(s4, 0.f);
    }
    __syncthreads();

    float s5 = bc[n];
    #pragma unroll 8
    for (int k = 0; k < 768; k++) s5 += comb[k] * Wc[k*256 + n];
    g_state[row*256 + n] = fmaxf(s5, 0.f);
}

// ---------------------------------------------------------------------------
// K2: HMMA fp16 GEMM (mma.sync.m16n8k16 — baseline sm_103 feature):
// G = x @ Wk + bl.  M=130560, N=1024, K=256.
// CTA tile 128x128, 8 warps (4M x 2N), warp tile 32x64, BK=64 (4 chunks).
// A f32->f16 during load; B from g_WkT. Pad-72 smem rows: ldmatrix rows hit
// distinct 16B banks (144B stride) -> conflict-free. fp32 accumulate.
// ---------------------------------------------------------------------------
__global__ void __launch_bounds__(256, 2) xwk_mma_kernel(
    const float* __restrict__ hist, const float* __restrict__ act,
    const float* __restrict__ bl)
{
    __shared__ __half A_s[128][72];
    __shared__ __half B_s[128][72];

    const int tid  = threadIdx.x;
    const int lane = tid & 31;
    const int wid  = tid >> 5;
    const int wm   = wid >> 1;          // 0..3  (M warp)
    const int wn   = wid & 1;           // 0..1  (N warp)
    const int bn0  = blockIdx.x * 128;
    const int bm0  = blockIdx.y * 128;

    float acc[2][8][4];
    #pragma unroll
    for (int i = 0; i < 2; i++)
        #pragma unroll
        for (int j = 0; j < 8; j++)
            #pragma unroll
            for (int q = 0; q < 4; q++) acc[i][j][q] = 0.f;

    for (int kc = 0; kc < 256; kc += 64) {
        // --- load A chunk: 128 rows x 64 halves (f32 -> f16) ---
        #pragma unroll
        for (int it = 0; it < 4; it++) {
            const int slot = it * 256 + tid;      // 0..1023
            const int row  = slot >> 3;           // 0..127
            const int k8   = (slot & 7) * 8;      // 0..56
            const int m    = bm0 + row;
            const int t    = m >> 9, b = m & 511;
            const float* src = (t < 127)
                ? (hist + ((size_t)b * STEPS + t) * DIN + kc + k8)
                : (act  + ((size_t)b * STEPS + (t - 127)) * DIN + kc + k8);
            float4 f0 = *(const float4*)src;
            float4 f1 = *(const float4*)(src + 4);
            __half2 h0 = __floats2half2_rn(f0.x, f0.y);
            __half2 h1 = __floats2half2_rn(f0.z, f0.w);
            __half2 h2 = __floats2half2_rn(f1.x, f1.y);
            __half2 h3 = __floats2half2_rn(f1.z, f1.w);
            uint4 v;
            v.x = *(uint32_t*)&h0; v.y = *(uint32_t*)&h1;
            v.z = *(uint32_t*)&h2; v.w = *(uint32_t*)&h3;
            *(uint4*)&A_s[row][k8] = v;
        }
        // --- load B chunk: 128 n-rows x 64 halves from g_WkT ---
        #pragma unroll
        for (int it = 0; it < 4; it++) {
            const int slot = it * 256 + tid;
            const int n    = slot >> 3;
            const int k8   = (slot & 7) * 8;
            uint4 v = *(const uint4*)(g_WkT + (size_t)(bn0 + n) * 256 + kc + k8);
            *(uint4*)&B_s[n][k8] = v;
        }
        __syncthreads();

        #pragma unroll
        for (int ks = 0; ks < 4; ks++) {
            const int kb = ks * 16 + ((lane >> 4) << 3);
            uint32_t af[2][4];
            #pragma unroll
            for (int im = 0; im < 2; im++) {
                uint32_t a = smem_u32(&A_s[wm*32 + im*16 + (lane & 15)][kb]);
                ldsm4(af[im][0], af[im][1], af[im][2], af[im][3], a);
            }
            uint32_t bf[4][4];
            #pragma unroll
            for (int g = 0; g < 4; g++) {
                uint32_t a = smem_u32(&B_s[wn*64 + g*16 + (lane & 15)][kb]);
                ldsm4(bf[g][0], bf[g][1], bf[g][2], bf[g][3], a);
            }
            #pragma unroll
            for (int im = 0; im < 2; im++)
                #pragma unroll
                for (int g = 0; g < 4; g++) {
                    mma16816(acc[im][g*2],     af[im], bf[g][0], bf[g][2]);
                    mma16816(acc[im][g*2 + 1], af[im], bf[g][1], bf[g][3]);
                }
        }
        __syncthreads();
    }

    // --- epilogue: +bl, float2 stores ---
    const int r  = lane >> 2;
    const int c2 = (lane & 3) * 2;
    #pragma unroll
    for (int im = 0; im < 2; im++) {
        #pragma unroll
        for (int j = 0; j < 8; j++) {
            const int gm = bm0 + wm*32 + im*16 + r;
            const int gn = bn0 + wn*64 + j*8 + c2;
            const float b0 = bl[gn], b1 = bl[gn + 1];
            *(float2*)(g_G + (size_t)gm * G4 + gn) =
                make_float2(acc[im][j][0] + b0, acc[im][j][1] + b1);
            *(float2*)(g_G + (size_t)(gm + 8) * G4 + gn) =
                make_float2(acc[im][j][2] + b0, acc[im][j][3] + b1);
        }
    }
}

// ---------------------------------------------------------------------------
// K3: persistent LSTM recurrence (unchanged from R10 best).
// 128 CTAs x 4 batch rows, 512 threads, k-split halves, fp16 W stream.
// ---------------------------------------------------------------------------
__global__ void __launch_bounds__(512, 1) recur_kernel()
{
    __shared__ float2 hs2[RROWS][256];
    __shared__ float4 part[RROWS][256];

    const int tid  = threadIdx.x;
    const int n    = tid & 255;
    const int half = tid >> 8;
    const int r0   = blockIdx.x * RROWS;

    float c[RROWS];
    if (half == 0) {
        #pragma unroll
        for (int r = 0; r < RROWS; r++) {
            c[r] = g_state[(r0 + r) * 256 + n];
            hs2[r][n] = make_float2(c[r], c[r]);
        }
    }
    __syncthreads();

    const uint4* wp = g_Whp + (size_t)(half * 64) * 256 + n;
    const int kbase = half * 128;

    for (int t = 0; t < TSTEPS; t++) {
        float gz[RROWS][4];
        if (half == 0) {
            #pragma unroll
            for (int r = 0; r < RROWS; r++) {
                const float* Gp = g_G + ((size_t)t * BATCH + r0 + r) * G4 + n;
                gz[r][0] = Gp[0];   gz[r][1] = Gp[256];
                gz[r][2] = Gp[512]; gz[r][3] = Gp[768];
            }
        }

        unsigned long long accif[RROWS], accgo[RROWS];
        #pragma unroll
        for (int r = 0; r < RROWS; r++) { accif[r] = 0ull; accgo[r] = 0ull; }

        #pragma unroll 4
        for (int kp = 0; kp < 64; kp++) {
            const uint4 w = wp[(size_t)kp * 256];
            const unsigned long long wif0 = h2f2(w.x);
            const unsigned long long wgo0 = h2f2(w.y);
            const unsigned long long wif1 = h2f2(w.z);
            const unsigned long long wgo1 = h2f2(w.w);
            #pragma unroll
            for (int r = 0; r < RROWS; r++) {
                F4U hh; hh.f = *(const float4*)&hs2[r][kbase + 2*kp];
                fma2(accif[r], wif0, hh.u.x);
                fma2(accgo[r], wgo0, hh.u.x);
                fma2(accif[r], wif1, hh.u.y);
                fma2(accgo[r], wgo1, hh.u.y);
            }
        }

        if (half == 1) {
            #pragma unroll
            for (int r = 0; r < RROWS; r++) {
                F4U p; p.u.x = accif[r]; p.u.y = accgo[r];
                part[r][n] = p.f;
            }
        }
        __syncthreads();

        if (half == 0) {
            #pragma unroll
            for (int r = 0; r < RROWS; r++) {
                F4U p; p.f = part[r][n];
                F2U eif, ego; eif.u = accif[r]; ego.u = accgo[r];
                const float zi = eif.f.x + p.f.x + gz[r][0];
                const float zf = eif.f.y + p.f.y + gz[r][1];
                const float zg = ego.f.x + p.f.z + gz[r][2];
                const float zo = ego.f.y + p.f.w + gz[r][3];
                const float ig = sigm(zi);
                const float fg = sigm(zf);
                const float gg = tanha(zg);
                const float og = sigm(zo);
                c[r] = fg * c[r] + ig * gg;
                const float h = og * tanha(c[r]);
                hs2[r][n] = make_float2(h, h);
            }
        }
        __syncthreads();
    }

    if (half == 0) {
        #pragma unroll
        for (int r = 0; r < RROWS; r++)
            g_h[(r0 + r) * 256 + n] = hs2[r][n].x;
    }
}

// ---------------------------------------------------------------------------
// K4: out = relu(h @ Wo + bo), [512,1]. One warp per batch row.
// ---------------------------------------------------------------------------
__global__ void out_kernel(const float* __restrict__ Wo,
                           const float* __restrict__ bo,
                           float* __restrict__ out)
{
    const int b = blockIdx.x;
    const int lane = threadIdx.x;
    float s = 0.f;
    #pragma unroll
    for (int k = lane; k < 256; k += 32) s += g_h[b*256 + k] * Wo[k];
    #pragma unroll
    for (int off = 16; off; off >>= 1) s += __shfl_down_sync(0xffffffffu, s, off);
    if (lane == 0) out[b] = fmaxf(s + bo[0], 0.f);
}

// ---------------------------------------------------------------------------
extern "C" void kernel_launch(void* const* d_in, const int* in_sizes, int n_in,
                              void* d_out, int out_size)
{
    const float* motion = (const float*)d_in[0];
    const float* robot  = (const float*)d_in[1];
    const float* osr    = (const float*)d_in[2];
    const float* osi    = (const float*)d_in[3];
    const float* hist   = (const float*)d_in[4];
    const float* act    = (const float*)d_in[5];
    const float* orr_   = (const float*)d_in[6];
    const float* ori_   = (const float*)d_in[7];
    const float* Wm  = (const float*)d_in[8];
    const float* bm  = (const float*)d_in[9];
    const float* Wr  = (const float*)d_in[10];
    const float* br  = (const float*)d_in[11];
    const float* Wre = (const float*)d_in[12];
    const float* bre = (const float*)d_in[13];
    const float* Wim = (const float*)d_in[14];
    const float* bim = (const float*)d_in[15];
    const float* Wc  = (const float*)d_in[16];
    const float* bc  = (const float*)d_in[17];
    const float* Wk  = (const float*)d_in[18];
    const float* Wrk = (const float*)d_in[19];
    const float* bl  = (const float*)d_in[20];
    const float* Wo  = (const float*)d_in[21];
    const float* bo  = (const float*)d_in[22];
    float* out = (float*)d_out;

    reformat_wrk<<<128, 256>>>(Wrk);
    reformat_wk<<<1024, 256>>>(Wk);

    preamble_kernel<<<BATCH, 256>>>(motion, robot, osr, osi, orr_, ori_,
                                    Wm, bm, Wr, br, Wre, bre, Wim, bim, Wc, bc);

    dim3 g2(G4 / 128, (TSTEPS * BATCH) / 128);   // (8, 1020)
    xwk_mma_kernel<<<g2, 256>>>(hist, act, bl);

    recur_kernel<<<RCTAS, 512>>>();

    out_kernel<<<BATCH, 32>>>(Wo, bo, out);
}

// round 14
// speedup vs baseline: 1.9871x; 1.3902x over previous
#include <cuda_runtime.h>
#include <cuda_fp16.h>
#include <math.h>
#include <stdint.h>

#define BATCH   512
#define STEPS   128
#define TSTEPS  255          // 127 history + 128 action
#define DIN     256
#define UDIM    256
#define G4      1024         // 4*UDIM

// HMMA recurrence geometry
#define RMROWS  16           // batch rows per CTA
#define RMCTAS  (BATCH / RMROWS)   // 32
// dynamic smem: z_s [16][1032] f32, then h_s [16][264] f16
#define ZS_STRIDE 1032
#define ZS_BYTES  (16 * ZS_STRIDE * 4)        // 66048
#define HS_STRIDE 264
#define HS_BYTES  (16 * HS_STRIDE * 2)        // 8448
#define RM_SMEM   (ZS_BYTES + HS_BYTES)       // 74496

// Scratch (static device allocations — no cudaMalloc anywhere)
__device__ float  g_state[BATCH * UDIM];
__device__ float  g_h[BATCH * UDIM];
__device__ float  g_G[(size_t)TSTEPS * BATCH * G4];   // x@Wk + bl, [t][b][4U]
__device__ __half g_WkT[1024 * 256];  // fp16 Wk transposed: [n][k]
// Wrk in HMMA B-fragment layout: [ntile(128)][kp(8)][lane(32)] -> uint4
// uint4 = { b0(ks=2kp), b1(ks=2kp), b0(ks=2kp+1), b1(ks=2kp+1) }
__device__ uint4  g_WrkF[128 * 8 * 32];

// ---------------------------------------------------------------------------
// helpers
// ---------------------------------------------------------------------------
__device__ __forceinline__ float tanha(float x)
{
    float y; asm("tanh.approx.f32 %0, %1;" : "=f"(y) : "f"(x)); return y;
}
__device__ __forceinline__ float sigm(float x)
{
    return fmaf(0.5f, tanha(0.5f * x), 0.5f);
}
__device__ __forceinline__ uint32_t smem_u32(const void* p)
{
    uint32_t a;
    asm("{ .reg .u64 t; cvta.to.shared.u64 t, %1; cvt.u32.u64 %0, t; }"
        : "=r"(a) : "l"(p));
    return a;
}
__device__ __forceinline__ void ldsm4(uint32_t& r0, uint32_t& r1,
                                      uint32_t& r2, uint32_t& r3, uint32_t a)
{
    asm volatile("ldmatrix.sync.aligned.m8n8.x4.shared.b16 {%0,%1,%2,%3}, [%4];"
                 : "=r"(r0), "=r"(r1), "=r"(r2), "=r"(r3) : "r"(a));
}
__device__ __forceinline__ void mma16816(float* c, const uint32_t* a,
                                         uint32_t b0, uint32_t b1)
{
    asm volatile(
        "mma.sync.aligned.m16n8k16.row.col.f32.f16.f16.f32 "
        "{%0,%1,%2,%3}, {%4,%5,%6,%7}, {%8,%9}, {%0,%1,%2,%3};"
        : "+f"(c[0]), "+f"(c[1]), "+f"(c[2]), "+f"(c[3])
        : "r"(a[0]), "r"(a[1]), "r"(a[2]), "r"(a[3]), "r"(b0), "r"(b1));
}
__device__ __forceinline__ uint32_t pack_h2(float x, float y)
{
    __half2 h = __floats2half2_rn(x, y);
    return *(uint32_t*)&h;
}

// ---------------------------------------------------------------------------
// K0a: Wrk [256,1024] -> HMMA B-fragment layout g_WrkF
// ---------------------------------------------------------------------------
__global__ void reformat_wrkF(const float* __restrict__ Wrk)
{
    const int idx  = blockIdx.x * 256 + threadIdx.x;   // 32768
    const int lane = idx & 31;
    const int kp   = (idx >> 5) & 7;
    const int nt   = idx >> 8;                         // 0..127
    const int n    = nt * 8 + (lane >> 2);
    const int c2   = (lane & 3) * 2;
    const int k0   = kp * 32;
    const int k1   = k0 + 16;
    uint4 v;
    v.x = pack_h2(Wrk[(k0 + c2)     * G4 + n], Wrk[(k0 + c2 + 1) * G4 + n]);
    v.y = pack_h2(Wrk[(k0 + c2 + 8) * G4 + n], Wrk[(k0 + c2 + 9) * G4 + n]);
    v.z = pack_h2(Wrk[(k1 + c2)     * G4 + n], Wrk[(k1 + c2 + 1) * G4 + n]);
    v.w = pack_h2(Wrk[(k1 + c2 + 8) * G4 + n], Wrk[(k1 + c2 + 9) * G4 + n]);
    g_WrkF[idx] = v;
}

// ---------------------------------------------------------------------------
// K0b: Wk [256,1024] -> fp16 transposed [1024,256] (xwk B operand)
// ---------------------------------------------------------------------------
__global__ void reformat_wk(const float* __restrict__ Wk)
{
    const int n = blockIdx.x;            // 1024
    const int k = threadIdx.x;           // 256
    g_WkT[n * 256 + k] = __float2half_rn(Wk[(size_t)k * G4 + n]);
}

// ---------------------------------------------------------------------------
// K1: preamble — ms/rs/re/im + combine -> state [512,256]
// ---------------------------------------------------------------------------
__global__ void __launch_bounds__(256) preamble_kernel(
    const float* __restrict__ motion, const float* __restrict__ robot,
    const float* __restrict__ osr,    const float* __restrict__ osi,
    const float* __restrict__ orr_,   const float* __restrict__ ori_,
    const float* __restrict__ Wm, const float* __restrict__ bm,
    const float* __restrict__ Wr, const float* __restrict__ br,
    const float* __restrict__ Wre, const float* __restrict__ bre,
    const float* __restrict__ Wim, const float* __restrict__ bim,
    const float* __restrict__ Wc,  const float* __restrict__ bc)
{
    __shared__ float comb[768];
    const int row = blockIdx.x;
    const int n   = threadIdx.x;

    float s = bm[n];
    #pragma unroll 8
    for (int k = 0; k < 64; k++) s += motion[row*64 + k] * Wm[k*256 + n];
    comb[n] = fmaxf(s, 0.f);

    s = br[n];
    #pragma unroll 8
    for (int k = 0; k < 128; k++) s += robot[row*128 + k] * Wr[k*256 + n];
    comb[256 + n] = fmaxf(s, 0.f);

    if (n < 128) {
        float s3 = bre[n];
        #pragma unroll 8
        for (int k = 0; k < 64; k++) s3 += osr [row*64 + k] * Wre[k*128 + n];
        #pragma unroll 8
        for (int k = 0; k < 64; k++) s3 += orr_[row*64 + k] * Wre[(64+k)*128 + n];
        comb[512 + n] = fmaxf(s3, 0.f);
    } else {
        const int m = n - 128;
        float s4 = bim[m];
        #pragma unroll 8
        for (int k = 0; k < 64; k++) s4 += osi [row*64 + k] * Wim[k*128 + m];
        #pragma unroll 8
        for (int k = 0; k < 64; k++) s4 += ori_[row*64 + k] * Wim[(64+k)*128 + m];
        comb[640 + m] = fmaxf(s4, 0.f);
    }
    __syncthreads();

    float s5 = bc[n];
    #pragma unroll 8
    for (int k = 0; k < 768; k++) s5 += comb[k] * Wc[k*256 + n];
    g_state[row*256 + n] = fmaxf(s5, 0.f);
}

// ---------------------------------------------------------------------------
// K2: HMMA fp16 GEMM (unchanged R13 winner): G = x @ Wk + bl.
// ---------------------------------------------------------------------------
__global__ void __launch_bounds__(256, 2) xwk_mma_kernel(
    const float* __restrict__ hist, const float* __restrict__ act,
    const float* __restrict__ bl)
{
    __shared__ __half A_s[128][72];
    __shared__ __half B_s[128][72];

    const int tid  = threadIdx.x;
    const int lane = tid & 31;
    const int wid  = tid >> 5;
    const int wm   = wid >> 1;
    const int wn   = wid & 1;
    const int bn0  = blockIdx.x * 128;
    const int bm0  = blockIdx.y * 128;

    float acc[2][8][4];
    #pragma unroll
    for (int i = 0; i < 2; i++)
        #pragma unroll
        for (int j = 0; j < 8; j++)
            #pragma unroll
            for (int q = 0; q < 4; q++) acc[i][j][q] = 0.f;

    for (int kc = 0; kc < 256; kc += 64) {
        #pragma unroll
        for (int it = 0; it < 4; it++) {
            const int slot = it * 256 + tid;
            const int row  = slot >> 3;
            const int k8   = (slot & 7) * 8;
            const int m    = bm0 + row;
            const int t    = m >> 9, b = m & 511;
            const float* src = (t < 127)
                ? (hist + ((size_t)b * STEPS + t) * DIN + kc + k8)
                : (act  + ((size_t)b * STEPS + (t - 127)) * DIN + kc + k8);
            float4 f0 = *(const float4*)src;
            float4 f1 = *(const float4*)(src + 4);
            uint4 v;
            v.x = pack_h2(f0.x, f0.y); v.y = pack_h2(f0.z, f0.w);
            v.z = pack_h2(f1.x, f1.y); v.w = pack_h2(f1.z, f1.w);
            *(uint4*)&A_s[row][k8] = v;
        }
        #pragma unroll
        for (int it = 0; it < 4; it++) {
            const int slot = it * 256 + tid;
            const int n    = slot >> 3;
            const int k8   = (slot & 7) * 8;
            uint4 v = *(const uint4*)(g_WkT + (size_t)(bn0 + n) * 256 + kc + k8);
            *(uint4*)&B_s[n][k8] = v;
        }
        __syncthreads();

        #pragma unroll
        for (int ks = 0; ks < 4; ks++) {
            const int kb = ks * 16 + ((lane >> 4) << 3);
            uint32_t af[2][4];
            #pragma unroll
            for (int im = 0; im < 2; im++) {
                uint32_t a = smem_u32(&A_s[wm*32 + im*16 + (lane & 15)][kb]);
                ldsm4(af[im][0], af[im][1], af[im][2], af[im][3], a);
            }
            uint32_t bf[4][4];
            #pragma unroll
            for (int g = 0; g < 4; g++) {
                uint32_t a = smem_u32(&B_s[wn*64 + g*16 + (lane & 15)][kb]);
                ldsm4(bf[g][0], bf[g][1], bf[g][2], bf[g][3], a);
            }
            #pragma unroll
            for (int im = 0; im < 2; im++)
                #pragma unroll
                for (int g = 0; g < 4; g++) {
                    mma16816(acc[im][g*2],     af[im], bf[g][0], bf[g][2]);
                    mma16816(acc[im][g*2 + 1], af[im], bf[g][1], bf[g][3]);
                }
        }
        __syncthreads();
    }

    const int r  = lane >> 2;
    const int c2 = (lane & 3) * 2;
    #pragma unroll
    for (int im = 0; im < 2; im++) {
        #pragma unroll
        for (int j = 0; j < 8; j++) {
            const int gm = bm0 + wm*32 + im*16 + r;
            const int gn = bn0 + wn*64 + j*8 + c2;
            const float b0 = bl[gn], b1 = bl[gn + 1];
            *(float2*)(g_G + (size_t)gm * G4 + gn) =
                make_float2(acc[im][j][0] + b0, acc[im][j][1] + b1);
            *(float2*)(g_G + (size_t)(gm + 8) * G4 + gn) =
                make_float2(acc[im][j][2] + b0, acc[im][j][3] + b1);
        }
    }
}

// ---------------------------------------------------------------------------
// K3: HMMA LSTM recurrence. 32 CTAs x 16 batch rows, 512 threads (16 warps).
// Per step: warp w computes z[16 rows][n=64w..64w+64) via m16n8k16 HMMA
// (A = fp16 h in smem via ldmatrix; B = fragment-layout LDG.128 from L2),
// stores z to smem; gate phase (thread = row x 8 features, c in regs)
// applies activations and writes fp16 h for the next step. 2 bars/step,
// no cross-CTA coupling.
// ---------------------------------------------------------------------------
__global__ void __launch_bounds__(512, 1) recur_mma_kernel()
{
    extern __shared__ char smem[];
    float*  z_s = (float*)smem;                        // [16][1032]
    __half* h_s = (__half*)(smem + ZS_BYTES);          // [16][264]

    const int tid  = threadIdx.x;
    const int lane = tid & 31;
    const int w    = tid >> 5;           // warp id 0..15 (also gate row)
    const int r0   = blockIdx.x * RMROWS;
    const int f0   = (lane) * 8;         // gate feature base (tid&31)*8

    // init: c = h = state
    float c[8];
    {
        const float* sp = g_state + (size_t)(r0 + w) * 256 + f0;
        #pragma unroll
        for (int j = 0; j < 8; j++) c[j] = sp[j];
        uint4 hv;
        hv.x = pack_h2(c[0], c[1]); hv.y = pack_h2(c[2], c[3]);
        hv.z = pack_h2(c[4], c[5]); hv.w = pack_h2(c[6], c[7]);
        *(uint4*)&h_s[w * HS_STRIDE + f0] = hv;
    }
    __syncthreads();

    const uint4* bptr = g_WrkF + (size_t)(w * 8) * 8 * 32 + lane;
    const int zr = lane >> 2;            // acc row within tile
    const int zc = (lane & 3) * 2;       // acc col pair
    float hreg[8];

    #pragma unroll 1
    for (int t = 0; t < TSTEPS; t++) {
        float acc[8][4];
        #pragma unroll
        for (int nt = 0; nt < 8; nt++)
            #pragma unroll
            for (int q = 0; q < 4; q++) acc[nt][q] = 0.f;

        uint4 bf[8];
        #pragma unroll
        for (int nt = 0; nt < 8; nt++) bf[nt] = bptr[(nt * 8) * 32];

        #pragma unroll
        for (int kp = 0; kp < 8; kp++) {
            uint4 bc[8];
            #pragma unroll
            for (int nt = 0; nt < 8; nt++) bc[nt] = bf[nt];
            if (kp < 7) {
                #pragma unroll
                for (int nt = 0; nt < 8; nt++)
                    bf[nt] = bptr[(nt * 8 + kp + 1) * 32];
            }
            const int kb = kp * 32 + ((lane >> 4) << 3);
            uint32_t a0[4], a1[4];
            ldsm4(a0[0], a0[1], a0[2], a0[3],
                  smem_u32(&h_s[(lane & 15) * HS_STRIDE + kb]));
            ldsm4(a1[0], a1[1], a1[2], a1[3],
                  smem_u32(&h_s[(lane & 15) * HS_STRIDE + kb + 16]));
            #pragma unroll
            for (int nt = 0; nt < 8; nt++) {
                mma16816(acc[nt], a0, bc[nt].x, bc[nt].y);
                mma16816(acc[nt], a1, bc[nt].z, bc[nt].w);
            }
        }

        // store z fragments
        #pragma unroll
        for (int nt = 0; nt < 8; nt++) {
            const int n0 = w * 64 + nt * 8 + zc;
            *(float2*)&z_s[zr * ZS_STRIDE + n0] =
                make_float2(acc[nt][0], acc[nt][1]);
            *(float2*)&z_s[(zr + 8) * ZS_STRIDE + n0] =
                make_float2(acc[nt][2], acc[nt][3]);
        }
        __syncthreads();   // z ready; h_s reads done

        // gate phase: thread (row=w, features f0..f0+8)
        {
            const float* Gp = g_G + ((size_t)t * BATCH + r0 + w) * G4 + f0;
            float4 gi0 = *(const float4*)(Gp);
            float4 gi1 = *(const float4*)(Gp + 4);
            float4 gf0 = *(const float4*)(Gp + 256);
            float4 gf1 = *(const float4*)(Gp + 260);
            float4 gg0 = *(const float4*)(Gp + 512);
            float4 gg1 = *(const float4*)(Gp + 516);
            float4 go0 = *(const float4*)(Gp + 768);
            float4 go1 = *(const float4*)(Gp + 772);
            const float* gi = &gi0.x;  // gi0,gi1 contiguous on stack? avoid: use arrays
            float giA[8] = {gi0.x,gi0.y,gi0.z,gi0.w,gi1.x,gi1.y,gi1.z,gi1.w};
            float gfA[8] = {gf0.x,gf0.y,gf0.z,gf0.w,gf1.x,gf1.y,gf1.z,gf1.w};
            float ggA[8] = {gg0.x,gg0.y,gg0.z,gg0.w,gg1.x,gg1.y,gg1.z,gg1.w};
            float goA[8] = {go0.x,go0.y,go0.z,go0.w,go1.x,go1.y,go1.z,go1.w};
            (void)gi;
            const float* zrow = z_s + w * ZS_STRIDE;
            #pragma unroll
            for (int j = 0; j < 8; j++) {
                const float zi = zrow[f0 + j]       + giA[j];
                const float zf = zrow[256 + f0 + j] + gfA[j];
                const float zg = zrow[512 + f0 + j] + ggA[j];
                const float zo = zrow[768 + f0 + j] + goA[j];
                c[j] = sigm(zf) * c[j] + sigm(zi) * tanha(zg);
                hreg[j] = sigm(zo) * tanha(c[j]);
            }
        }
        __syncthreads();   // all z reads done before h_s overwrite

        {
            uint4 hv;
            hv.x = pack_h2(hreg[0], hreg[1]); hv.y = pack_h2(hreg[2], hreg[3]);
            hv.z = pack_h2(hreg[4], hreg[5]); hv.w = pack_h2(hreg[6], hreg[7]);
            *(uint4*)&h_s[w * HS_STRIDE + f0] = hv;
        }
        __syncthreads();   // h ready for next step
    }

    {
        float* hp = g_h + (size_t)(r0 + w) * 256 + f0;
        #pragma unroll
        for (int j = 0; j < 8; j++) hp[j] = hreg[j];
    }
}

// ---------------------------------------------------------------------------
// K4: out = relu(h @ Wo + bo), [512,1]. One warp per batch row.
// ---------------------------------------------------------------------------
__global__ void out_kernel(const float* __restrict__ Wo,
                           const float* __restrict__ bo,
                           float* __restrict__ out)
{
    const int b = blockIdx.x;
    const int lane = threadIdx.x;
    float s = 0.f;
    #pragma unroll
    for (int k = lane; k < 256; k += 32) s += g_h[b*256 + k] * Wo[k];
    #pragma unroll
    for (int off = 16; off; off >>= 1) s += __shfl_down_sync(0xffffffffu, s, off);
    if (lane == 0) out[b] = fmaxf(s + bo[0], 0.f);
}

// ---------------------------------------------------------------------------
extern "C" void kernel_launch(void* const* d_in, const int* in_sizes, int n_in,
                              void* d_out, int out_size)
{
    const float* motion = (const float*)d_in[0];
    const float* robot  = (const float*)d_in[1];
    const float* osr    = (const float*)d_in[2];
    const float* osi    = (const float*)d_in[3];
    const float* hist   = (const float*)d_in[4];
    const float* act    = (const float*)d_in[5];
    const float* orr_   = (const float*)d_in[6];
    const float* ori_   = (const float*)d_in[7];
    const float* Wm  = (const float*)d_in[8];
    const float* bm  = (const float*)d_in[9];
    const float* Wr  = (const float*)d_in[10];
    const float* br  = (const float*)d_in[11];
    const float* Wre = (const float*)d_in[12];
    const float* bre = (const float*)d_in[13];
    const float* Wim = (const float*)d_in[14];
    const float* bim = (const float*)d_in[15];
    const float* Wc  = (const float*)d_in[16];
    const float* bc  = (const float*)d_in[17];
    const float* Wk  = (const float*)d_in[18];
    const float* Wrk = (const float*)d_in[19];
    const float* bl  = (const float*)d_in[20];
    const float* Wo  = (const float*)d_in[21];
    const float* bo  = (const float*)d_in[22];
    float* out = (float*)d_out;

    static int smem_set = 0;
    if (!smem_set) {
        cudaFuncSetAttribute(recur_mma_kernel,
                             cudaFuncAttributeMaxDynamicSharedMemorySize, RM_SMEM);
        smem_set = 1;
    }

    reformat_wrkF<<<128, 256>>>(Wrk);
    reformat_wk<<<1024, 256>>>(Wk);

    preamble_kernel<<<BATCH, 256>>>(motion, robot, osr, osi, orr_, ori_,
                                    Wm, bm, Wr, br, Wre, bre, Wim, bim, Wc, bc);

    dim3 g2(G4 / 128, (TSTEPS * BATCH) / 128);   // (8, 1020)
    xwk_mma_kernel<<<g2, 256>>>(hist, act, bl);

    recur_mma_kernel<<<RMCTAS, 512, RM_SMEM>>>();

    out_kernel<<<BATCH, 32>>>(Wo, bo, out);
}

// round 16
// speedup vs baseline: 2.4578x; 1.2369x over previous
#include <cuda_runtime.h>
#include <cuda_fp16.h>
#include <math.h>
#include <stdint.h>

#define BATCH   512
#define STEPS   128
#define TSTEPS  255          // 127 history + 128 action
#define DIN     256
#define UDIM    256
#define G4      1024         // 4*UDIM

// fused kernel geometry
#define NRECUR  32                     // recur CTAs (16 rows each)
#define NXWK    ((TSTEPS*BATCH/128) * (G4/128))   // 1020*8 = 8160
#define NYB     (TSTEPS * BATCH / 128)            // 1020 y-blocks
#define YTARGET 8                      // xwk CTAs per y-block (1024/128)
#define HS_STRIDE 264
#define FUSED_SMEM (128*72*2*2)        // xwk A_s+B_s = 36864 (recur uses 8448)

// Scratch (static device allocations — no cudaMalloc anywhere)
__device__ float  g_state[BATCH * UDIM];
__device__ float  g_h[BATCH * UDIM];
__device__ float  g_G[(size_t)TSTEPS * BATCH * G4];   // x@Wk + bl, PERMUTED cols
__device__ __half g_WkT[1024 * 256];  // fp16 Wk transposed: [n][k]
// Wrk HMMA B-fragments, gate-blocked col order: [NT(128)][kp(8)][lane(32)]
__device__ uint4  g_WrkF[128 * 8 * 32];
__device__ int    g_cnt[NYB];         // per-y completion counters (target 8)

// ---------------------------------------------------------------------------
// helpers
// ---------------------------------------------------------------------------
__device__ __forceinline__ float tanha(float x)
{
    float y; asm("tanh.approx.f32 %0, %1;" : "=f"(y) : "f"(x)); return y;
}
__device__ __forceinline__ float sigm(float x)
{
    return fmaf(0.5f, tanha(0.5f * x), 0.5f);
}
__device__ __forceinline__ uint32_t smem_u32(const void* p)
{
    uint32_t a;
    asm("{ .reg .u64 t; cvta.to.shared.u64 t, %1; cvt.u32.u64 %0, t; }"
        : "=r"(a) : "l"(p));
    return a;
}
__device__ __forceinline__ void ldsm4(uint32_t& r0, uint32_t& r1,
                                      uint32_t& r2, uint32_t& r3, uint32_t a)
{
    asm volatile("ldmatrix.sync.aligned.m8n8.x4.shared.b16 {%0,%1,%2,%3}, [%4];"
                 : "=r"(r0), "=r"(r1), "=r"(r2), "=r"(r3) : "r"(a));
}
__device__ __forceinline__ void mma16816(float* c, const uint32_t* a,
                                         uint32_t b0, uint32_t b1)
{
    asm volatile(
        "mma.sync.aligned.m16n8k16.row.col.f32.f16.f16.f32 "
        "{%0,%1,%2,%3}, {%4,%5,%6,%7}, {%8,%9}, {%0,%1,%2,%3};"
        : "+f"(c[0]), "+f"(c[1]), "+f"(c[2]), "+f"(c[3])
        : "r"(a[0]), "r"(a[1]), "r"(a[2]), "r"(a[3]), "r"(b0), "r"(b1));
}
__device__ __forceinline__ uint32_t pack_h2(float x, float y)
{
    __half2 h = __floats2half2_rn(x, y);
    return *(uint32_t*)&h;
}

// ---------------------------------------------------------------------------
// K0: init counters (every launch — graph replays!)
// ---------------------------------------------------------------------------
__global__ void init_cnt()
{
    const int i = blockIdx.x * 256 + threadIdx.x;
    if (i < NYB) g_cnt[i] = 0;
}

// ---------------------------------------------------------------------------
// K0a: Wrk -> HMMA B-fragments in gate-blocked column order.
// Warp w tile = 64 new-cols: nt 0,1 = gate i (features 16w+0..15),
// nt 2,3 = f, nt 4,5 = g, nt 6,7 = o.  orig col = gate*256 + 16w + 8j + n8.
// ---------------------------------------------------------------------------
__global__ void reformat_wrkF(const float* __restrict__ Wrk)
{
    const int idx  = blockIdx.x * 256 + threadIdx.x;   // 32768
    const int lane = idx & 31;
    const int kp   = (idx >> 5) & 7;
    const int NT   = idx >> 8;                         // 0..127
    const int w    = NT >> 3;
    const int nt   = NT & 7;
    const int gate = nt >> 1;
    const int j    = nt & 1;
    const int n    = gate * 256 + 16 * w + 8 * j + (lane >> 2);
    const int c2   = (lane & 3) * 2;
    const int k0   = kp * 32;
    const int k1   = k0 + 16;
    uint4 v;
    v.x = pack_h2(Wrk[(k0 + c2)     * G4 + n], Wrk[(k0 + c2 + 1) * G4 + n]);
    v.y = pack_h2(Wrk[(k0 + c2 + 8) * G4 + n], Wrk[(k0 + c2 + 9) * G4 + n]);
    v.z = pack_h2(Wrk[(k1 + c2)     * G4 + n], Wrk[(k1 + c2 + 1) * G4 + n]);
    v.w = pack_h2(Wrk[(k1 + c2 + 8) * G4 + n], Wrk[(k1 + c2 + 9) * G4 + n]);
    g_WrkF[idx] = v;
}

// ---------------------------------------------------------------------------
// K0b: Wk [256,1024] -> fp16 transposed [1024,256]
// ---------------------------------------------------------------------------
__global__ void reformat_wk(const float* __restrict__ Wk)
{
    const int n = blockIdx.x;
    const int k = threadIdx.x;
    g_WkT[n * 256 + k] = __float2half_rn(Wk[(size_t)k * G4 + n]);
}

// ---------------------------------------------------------------------------
// K1: preamble — ms/rs/re/im + combine -> state [512,256]
// ---------------------------------------------------------------------------
__global__ void __launch_bounds__(256) preamble_kernel(
    const float* __restrict__ motion, const float* __restrict__ robot,
    const float* __restrict__ osr,    const float* __restrict__ osi,
    const float* __restrict__ orr_,   const float* __restrict__ ori_,
    const float* __restrict__ Wm, const float* __restrict__ bm,
    const float* __restrict__ Wr, const float* __restrict__ br,
    const float* __restrict__ Wre, const float* __restrict__ bre,
    const float* __restrict__ Wim, const float* __restrict__ bim,
    const float* __restrict__ Wc,  const float* __restrict__ bc)
{
    __shared__ float comb[768];
    const int row = blockIdx.x;
    const int n   = threadIdx.x;

    float s = bm[n];
    #pragma unroll 8
    for (int k = 0; k < 64; k++) s += motion[row*64 + k] * Wm[k*256 + n];
    comb[n] = fmaxf(s, 0.f);

    s = br[n];
    #pragma unroll 8
    for (int k = 0; k < 128; k++) s += robot[row*128 + k] * Wr[k*256 + n];
    comb[256 + n] = fmaxf(s, 0.f);

    if (n < 128) {
        float s3 = bre[n];
        #pragma unroll 8
        for (int k = 0; k < 64; k++) s3 += osr [row*64 + k] * Wre[k*128 + n];
        #pragma unroll 8
        for (int k = 0; k < 64; k++) s3 += orr_[row*64 + k] * Wre[(64+k)*128 + n];
        comb[512 + n] = fmaxf(s3, 0.f);
    } else {
        const int m = n - 128;
        float s4 = bim[m];
        #pragma unroll 8
        for (int k = 0; k < 64; k++) s4 += osi [row*64 + k] * Wim[k*128 + m];
        #pragma unroll 8
        for (int k = 0; k < 64; k++) s4 += ori_[row*64 + k] * Wim[(64+k)*128 + m];
        comb[640 + m] = fmaxf(s4, 0.f);
    }
    __syncthreads();

    float s5 = bc[n];
    #pragma unroll 8
    for (int k = 0; k < 768; k++) s5 += comb[k] * Wc[k*256 + n];
    g_state[row*256 + n] = fmaxf(s5, 0.f);
}

// ---------------------------------------------------------------------------
// xwk body (producer): 512 threads, tile 128x128, BK=64, warp grid 4x4,
// warp tile 32x32. Writes G with PERMUTED columns, then bumps g_cnt[y].
// ---------------------------------------------------------------------------
__device__ __forceinline__ void xwk_body(
    char* smem, int bid,
    const float* __restrict__ hist, const float* __restrict__ act,
    const float* __restrict__ bl)
{
    __half (*A_s)[72] = (__half(*)[72])smem;
    __half (*B_s)[72] = (__half(*)[72])(smem + 128 * 72 * 2);

    const int tid  = threadIdx.x;
    const int lane = tid & 31;
    const int wid  = tid >> 5;
    const int wm   = wid >> 2;           // 0..3
    const int wn   = wid & 3;            // 0..3
    const int bx   = bid & 7;            // 0..7  (n-block of 128)
    const int by   = bid >> 3;           // 0..1019
    const int bn0  = bx * 128;
    const int bm0  = by * 128;

    float acc[2][4][4];
    #pragma unroll
    for (int i = 0; i < 2; i++)
        #pragma unroll
        for (int j = 0; j < 4; j++)
            #pragma unroll
            for (int q = 0; q < 4; q++) acc[i][j][q] = 0.f;

    for (int kc = 0; kc < 256; kc += 64) {
        #pragma unroll
        for (int it = 0; it < 2; it++) {
            const int slot = it * 512 + tid;      // 0..1023
            const int row  = slot >> 3;
            const int k8   = (slot & 7) * 8;
            const int m    = bm0 + row;
            const int t    = m >> 9, b = m & 511;
            const float* src = (t < 127)
                ? (hist + ((size_t)b * STEPS + t) * DIN + kc + k8)
                : (act  + ((size_t)b * STEPS + (t - 127)) * DIN + kc + k8);
            float4 f0 = *(const float4*)src;
            float4 f1 = *(const float4*)(src + 4);
            uint4 v;
            v.x = pack_h2(f0.x, f0.y); v.y = pack_h2(f0.z, f0.w);
            v.z = pack_h2(f1.x, f1.y); v.w = pack_h2(f1.z, f1.w);
            *(uint4*)&A_s[row][k8] = v;
        }
        #pragma unroll
        for (int it = 0; it < 2; it++) {
            const int slot = it * 512 + tid;
            const int n    = slot >> 3;
            const int k8   = (slot & 7) * 8;
            *(uint4*)&B_s[n][k8] =
                *(const uint4*)(g_WkT + (size_t)(bn0 + n) * 256 + kc + k8);
        }
        __syncthreads();

        #pragma unroll
        for (int ks = 0; ks < 4; ks++) {
            const int kb = ks * 16 + ((lane >> 4) << 3);
            uint32_t af[2][4];
            #pragma unroll
            for (int im = 0; im < 2; im++)
                ldsm4(af[im][0], af[im][1], af[im][2], af[im][3],
                      smem_u32(&A_s[wm*32 + im*16 + (lane & 15)][kb]));
            uint32_t bq[2][4];
            #pragma unroll
            for (int g2 = 0; g2 < 2; g2++)
                ldsm4(bq[g2][0], bq[g2][1], bq[g2][2], bq[g2][3],
                      smem_u32(&B_s[wn*32 + g2*16 + (lane & 15)][kb]));
            #pragma unroll
            for (int im = 0; im < 2; im++)
                #pragma unroll
                for (int g2 = 0; g2 < 2; g2++) {
                    mma16816(acc[im][g2*2],     af[im], bq[g2][0], bq[g2][2]);
                    mma16816(acc[im][g2*2 + 1], af[im], bq[g2][1], bq[g2][3]);
                }
        }
        __syncthreads();
    }

    // epilogue: +bl (orig col), store to PERMUTED col
    const int r  = lane >> 2;
    const int c2 = (lane & 3) * 2;
    #pragma unroll
    for (int im = 0; im < 2; im++) {
        #pragma unroll
        for (int nt = 0; nt < 4; nt++) {
            const int gm  = bm0 + wm*32 + im*16 + r;
            const int gnO = bn0 + wn*32 + nt*8 + c2;      // original column
            const int f   = gnO & 255, g = gnO >> 8;
            const int nc  = ((f >> 4) << 6) + (g << 4) + (f & 15);
            const float b0 = bl[gnO], b1 = bl[gnO + 1];
            *(float2*)(g_G + (size_t)gm * G4 + nc) =
                make_float2(acc[im][nt][0] + b0, acc[im][nt][1] + b1);
            *(float2*)(g_G + (size_t)(gm + 8) * G4 + nc) =
                make_float2(acc[im][nt][2] + b0, acc[im][nt][3] + b1);
        }
    }

    __threadfence();
    __syncthreads();
    if (tid == 0) atomicAdd(&g_cnt[by], 1);
}

// ---------------------------------------------------------------------------
// recur body (consumer): 16 rows, gates in fragment registers, c resident.
// Waits on g_cnt[4t + bid/8] == YTARGET before consuming G[t] rows.
// ---------------------------------------------------------------------------
__device__ __forceinline__ void recur_body(char* smem)
{
    __half* h_s = (__half*)smem;          // [16][264]

    const int tid  = threadIdx.x;
    const int lane = tid & 31;
    const int w    = tid >> 5;            // warp = 16-feature slice
    const int r0   = blockIdx.x * 16;
    const int zr   = lane >> 2;
    const int zc   = (lane & 3) * 2;
    const int yb   = blockIdx.x >> 3;     // r0 >> 7

    // init c = h = state (fragment layout)
    float c[2][4];
    #pragma unroll
    for (int nt0 = 0; nt0 < 2; nt0++) {
        const int feat = 16*w + nt0*8 + zc;
        c[nt0][0] = g_state[(size_t)(r0 + zr) * 256 + feat];
        c[nt0][1] = g_state[(size_t)(r0 + zr) * 256 + feat + 1];
        c[nt0][2] = g_state[(size_t)(r0 + zr + 8) * 256 + feat];
        c[nt0][3] = g_state[(size_t)(r0 + zr + 8) * 256 + feat + 1];
        *(uint32_t*)&h_s[zr       * HS_STRIDE + feat] = pack_h2(c[nt0][0], c[nt0][1]);
        *(uint32_t*)&h_s[(zr + 8) * HS_STRIDE + feat] = pack_h2(c[nt0][2], c[nt0][3]);
    }
    if (tid == 0) {
        while (*(volatile int*)&g_cnt[yb] < YTARGET) __nanosleep(128);
    }
    __syncthreads();

    const uint4* bptr = g_WrkF + (size_t)(w * 8) * 8 * 32 + lane;
    float h[2][4];

    #pragma unroll 1
    for (int t = 0; t < TSTEPS; t++) {
        float acc[8][4];
        #pragma unroll
        for (int nt = 0; nt < 8; nt++)
            #pragma unroll
            for (int q = 0; q < 4; q++) acc[nt][q] = 0.f;

        uint4 bf[8];
        #pragma unroll
        for (int nt = 0; nt < 8; nt++) bf[nt] = bptr[(nt * 8) * 32];

        #pragma unroll
        for (int kp = 0; kp < 8; kp++) {
            uint4 bc[8];
            #pragma unroll
            for (int nt = 0; nt < 8; nt++) bc[nt] = bf[nt];
            if (kp < 7) {
                #pragma unroll
                for (int nt = 0; nt < 8; nt++)
                    bf[nt] = bptr[(nt * 8 + kp + 1) * 32];
            }
            const int kb = kp * 32 + ((lane >> 4) << 3);
            uint32_t a0[4], a1[4];
            ldsm4(a0[0], a0[1], a0[2], a0[3],
                  smem_u32(&h_s[(lane & 15) * HS_STRIDE + kb]));
            ldsm4(a1[0], a1[1], a1[2], a1[3],
                  smem_u32(&h_s[(lane & 15) * HS_STRIDE + kb + 16]));
            #pragma unroll
            for (int nt = 0; nt < 8; nt++) {
                mma16816(acc[nt], a0, bc[nt].x, bc[nt].y);
                mma16816(acc[nt], a1, bc[nt].z, bc[nt].w);
            }
        }
        __syncthreads();   // all h_s reads done

        // gate math in fragment registers (G is in permuted col space)
        const float* Gb = g_G + ((size_t)t * BATCH + r0) * G4;
        float2 ga[8][2];
        #pragma unroll
        for (int nt = 0; nt < 8; nt++) {
            const int nc = 64*w + nt*8 + zc;
            ga[nt][0] = __ldcg((const float2*)(Gb + (size_t)zr * G4 + nc));
            ga[nt][1] = __ldcg((const float2*)(Gb + (size_t)(zr + 8) * G4 + nc));
        }
        #pragma unroll
        for (int nt0 = 0; nt0 < 2; nt0++) {
            #pragma unroll
            for (int q = 0; q < 4; q++) {
                const int rh = q >> 1;
                const float gi = (q & 1) ? ga[0 + nt0][rh].y : ga[0 + nt0][rh].x;
                const float gf = (q & 1) ? ga[2 + nt0][rh].y : ga[2 + nt0][rh].x;
                const float gg = (q & 1) ? ga[4 + nt0][rh].y : ga[4 + nt0][rh].x;
                const float go = (q & 1) ? ga[6 + nt0][rh].y : ga[6 + nt0][rh].x;
                const float zi = acc[0 + nt0][q] + gi;
                const float zf = acc[2 + nt0][q] + gf;
                const float zg = acc[4 + nt0][q] + gg;
                const float zo = acc[6 + nt0][q] + go;
                c[nt0][q] = sigm(zf) * c[nt0][q] + sigm(zi) * tanha(zg);
                h[nt0][q] = sigm(zo) * tanha(c[nt0][q]);
            }
        }

        // write new h (after sync1, so no reader conflict)
        #pragma unroll
        for (int nt0 = 0; nt0 < 2; nt0++) {
            const int feat = 16*w + nt0*8 + zc;
            *(uint32_t*)&h_s[zr       * HS_STRIDE + feat] = pack_h2(h[nt0][0], h[nt0][1]);
            *(uint32_t*)&h_s[(zr + 8) * HS_STRIDE + feat] = pack_h2(h[nt0][2], h[nt0][3]);
        }
        // overlap: poll next step's counter while others finish writes
        if (tid == 0 && t + 1 < TSTEPS) {
            const int y = 4 * (t + 1) + yb;
            while (*(volatile int*)&g_cnt[y] < YTARGET) __nanosleep(128);
        }
        __syncthreads();   // h visible; counter satisfied
    }

    // final h -> g_h (natural layout)
    #pragma unroll
    for (int nt0 = 0; nt0 < 2; nt0++) {
        const int feat = 16*w + nt0*8 + zc;
        *(float2*)(g_h + (size_t)(r0 + zr) * 256 + feat) =
            make_float2(h[nt0][0], h[nt0][1]);
        *(float2*)(g_h + (size_t)(r0 + zr + 8) * 256 + feat) =
            make_float2(h[nt0][2], h[nt0][3]);
    }
}

// ---------------------------------------------------------------------------
// K2: fused producer/consumer kernel. bid 0..31 = recur, 32.. = xwk.
// ---------------------------------------------------------------------------
__global__ void __launch_bounds__(512, 1) fused_kernel(
    const float* __restrict__ hist, const float* __restrict__ act,
    const float* __restrict__ bl)
{
    extern __shared__ char smem[];
    if (blockIdx.x < NRECUR) recur_body(smem);
    else                     xwk_body(smem, blockIdx.x - NRECUR, hist, act, bl);
}

// ---------------------------------------------------------------------------
// K4: out = relu(h @ Wo + bo), [512,1]. One warp per batch row.
// ---------------------------------------------------------------------------
__global__ void out_kernel(const float* __restrict__ Wo,
                           const float* __restrict__ bo,
                           float* __restrict__ out)
{
    const int b = blockIdx.x;
    const int lane = threadIdx.x;
    float s = 0.f;
    #pragma unroll
    for (int k = lane; k < 256; k += 32) s += g_h[b*256 + k] * Wo[k];
    #pragma unroll
    for (int off = 16; off; off >>= 1) s += __shfl_down_sync(0xffffffffu, s, off);
    if (lane == 0) out[b] = fmaxf(s + bo[0], 0.f);
}

// ---------------------------------------------------------------------------
extern "C" void kernel_launch(void* const* d_in, const int* in_sizes, int n_in,
                              void* d_out, int out_size)
{
    const float* motion = (const float*)d_in[0];
    const float* robot  = (const float*)d_in[1];
    const float* osr    = (const float*)d_in[2];
    const float* osi    = (const float*)d_in[3];
    const float* hist   = (const float*)d_in[4];
    const float* act    = (const float*)d_in[5];
    const float* orr_   = (const float*)d_in[6];
    const float* ori_   = (const float*)d_in[7];
    const float* Wm  = (const float*)d_in[8];
    const float* bm  = (const float*)d_in[9];
    const float* Wr  = (const float*)d_in[10];
    const float* br  = (const float*)d_in[11];
    const float* Wre = (const float*)d_in[12];
    const float* bre = (const float*)d_in[13];
    const float* Wim = (const float*)d_in[14];
    const float* bim = (const float*)d_in[15];
    const float* Wc  = (const float*)d_in[16];
    const float* bc  = (const float*)d_in[17];
    const float* Wk  = (const float*)d_in[18];
    const float* Wrk = (const float*)d_in[19];
    const float* bl  = (const float*)d_in[20];
    const float* Wo  = (const float*)d_in[21];
    const float* bo  = (const float*)d_in[22];
    float* out = (float*)d_out;

    static int smem_set = 0;
    if (!smem_set) {
        cudaFuncSetAttribute(fused_kernel,
                             cudaFuncAttributeMaxDynamicSharedMemorySize, FUSED_SMEM);
        smem_set = 1;
    }

    init_cnt<<<(NYB + 255) / 256, 256>>>();
    reformat_wrkF<<<128, 256>>>(Wrk);
    reformat_wk<<<1024, 256>>>(Wk);

    preamble_kernel<<<BATCH, 256>>>(motion, robot, osr, osi, orr_, ori_,
                                    Wm, bm, Wr, br, Wre, bre, Wim, bim, Wc, bc);

    fused_kernel<<<NRECUR + NXWK, 512, FUSED_SMEM>>>(hist, act, bl);

    out_kernel<<<BATCH, 32>>>(Wo, bo, out);
}

// round 17
// speedup vs baseline: 2.5435x; 1.0348x over previous
#include <cuda_runtime.h>
#include <cuda_fp16.h>
#include <math.h>
#include <stdint.h>

#define BATCH   512
#define STEPS   128
#define TSTEPS  255          // 127 history + 128 action
#define DIN     256
#define UDIM    256
#define G4      1024         // 4*UDIM

// fused kernel geometry
#define NRECUR  64                     // recur CTAs (pairs of 2 per 16 rows)
#define NXWK    ((TSTEPS*BATCH/128) * (G4/128))   // 1020*8 = 8160
#define NYB     (TSTEPS * BATCH / 128)            // 1020 y-blocks
#define YTARGET 8                      // xwk CTAs per y-block (1024/128)
#define HS_STRIDE 264
#define FUSED_SMEM (128*72*2*2)        // xwk A_s+B_s = 36864 (recur uses 8448)

// Scratch (static device allocations — no cudaMalloc anywhere)
__device__ float  g_state[BATCH * UDIM];
__device__ float  g_h[BATCH * UDIM];
__device__ float  g_G[(size_t)TSTEPS * BATCH * G4];   // x@Wk + bl, PERMUTED cols
__device__ __half g_WkT[1024 * 256];  // fp16 Wk transposed: [n][k]
// Wrk HMMA B-fragments, gate-blocked col order: [NT(128)][kp(8)][lane(32)]
__device__ uint4  g_WrkF[128 * 8 * 32];
__device__ int    g_cnt[NYB];         // per-y completion counters (target 8)
__device__ __half g_hx[BATCH * 256];  // per-step h exchange (fp16)
__device__ int    g_hf[NRECUR];       // per-CTA h-half step flags

// ---------------------------------------------------------------------------
// helpers
// ---------------------------------------------------------------------------
union F2U { float2 f; unsigned long long u; };

__device__ __forceinline__ void fma2(unsigned long long& d,
                                     unsigned long long a,
                                     unsigned long long b)
{
    asm("fma.rn.f32x2 %0, %1, %2, %0;" : "+l"(d) : "l"(a), "l"(b));
}
__device__ __forceinline__ unsigned long long dup2(float x)
{
    F2U t; t.f = make_float2(x, x); return t.u;
}
__device__ __forceinline__ float tanha(float x)
{
    float y; asm("tanh.approx.f32 %0, %1;" : "=f"(y) : "f"(x)); return y;
}
__device__ __forceinline__ float sigm(float x)
{
    return fmaf(0.5f, tanha(0.5f * x), 0.5f);
}
__device__ __forceinline__ uint32_t smem_u32(const void* p)
{
    uint32_t a;
    asm("{ .reg .u64 t; cvta.to.shared.u64 t, %1; cvt.u32.u64 %0, t; }"
        : "=r"(a) : "l"(p));
    return a;
}
__device__ __forceinline__ void ldsm4(uint32_t& r0, uint32_t& r1,
                                      uint32_t& r2, uint32_t& r3, uint32_t a)
{
    asm volatile("ldmatrix.sync.aligned.m8n8.x4.shared.b16 {%0,%1,%2,%3}, [%4];"
                 : "=r"(r0), "=r"(r1), "=r"(r2), "=r"(r3) : "r"(a));
}
__device__ __forceinline__ void mma16816(float* c, const uint32_t* a,
                                         uint32_t b0, uint32_t b1)
{
    asm volatile(
        "mma.sync.aligned.m16n8k16.row.col.f32.f16.f16.f32 "
        "{%0,%1,%2,%3}, {%4,%5,%6,%7}, {%8,%9}, {%0,%1,%2,%3};"
        : "+f"(c[0]), "+f"(c[1]), "+f"(c[2]), "+f"(c[3])
        : "r"(a[0]), "r"(a[1]), "r"(a[2]), "r"(a[3]), "r"(b0), "r"(b1));
}
__device__ __forceinline__ uint32_t pack_h2(float x, float y)
{
    __half2 h = __floats2half2_rn(x, y);
    return *(uint32_t*)&h;
}

// ---------------------------------------------------------------------------
// K0: init counters (every launch — graph replays!)
// ---------------------------------------------------------------------------
__global__ void init_cnt()
{
    const int i = blockIdx.x * 256 + threadIdx.x;
    if (i < NYB) g_cnt[i] = 0;
    if (i < NRECUR) g_hf[i] = 0;
}

// ---------------------------------------------------------------------------
// K0a: Wrk -> HMMA B-fragments in gate-blocked column order.
// NT = w*8 + nt, nt = 2*gate + j; orig col = gate*256 + 16w + 8j + n8.
// ---------------------------------------------------------------------------
__global__ void reformat_wrkF(const float* __restrict__ Wrk)
{
    const int idx  = blockIdx.x * 256 + threadIdx.x;   // 32768
    const int lane = idx & 31;
    const int kp   = (idx >> 5) & 7;
    const int NT   = idx >> 8;                         // 0..127
    const int w    = NT >> 3;
    const int nt   = NT & 7;
    const int gate = nt >> 1;
    const int j    = nt & 1;
    const int n    = gate * 256 + 16 * w + 8 * j + (lane >> 2);
    const int c2   = (lane & 3) * 2;
    const int k0   = kp * 32;
    const int k1   = k0 + 16;
    uint4 v;
    v.x = pack_h2(Wrk[(k0 + c2)     * G4 + n], Wrk[(k0 + c2 + 1) * G4 + n]);
    v.y = pack_h2(Wrk[(k0 + c2 + 8) * G4 + n], Wrk[(k0 + c2 + 9) * G4 + n]);
    v.z = pack_h2(Wrk[(k1 + c2)     * G4 + n], Wrk[(k1 + c2 + 1) * G4 + n]);
    v.w = pack_h2(Wrk[(k1 + c2 + 8) * G4 + n], Wrk[(k1 + c2 + 9) * G4 + n]);
    g_WrkF[idx] = v;
}

// ---------------------------------------------------------------------------
// K0b: Wk [256,1024] -> fp16 transposed [1024,256]
// ---------------------------------------------------------------------------
__global__ void reformat_wk(const float* __restrict__ Wk)
{
    const int n = blockIdx.x;
    const int k = threadIdx.x;
    g_WkT[n * 256 + k] = __float2half_rn(Wk[(size_t)k * G4 + n]);
}

// ---------------------------------------------------------------------------
// K1: preamble v2 — 64 CTAs x 8 rows; weights read once per CTA, FFMA2 rows.
// comb stored [k][r] so phase B gets broadcast LDS.128.
// ---------------------------------------------------------------------------
__global__ void __launch_bounds__(256) preamble_kernel(
    const float* __restrict__ motion, const float* __restrict__ robot,
    const float* __restrict__ osr,    const float* __restrict__ osi,
    const float* __restrict__ orr_,   const float* __restrict__ ori_,
    const float* __restrict__ Wm, const float* __restrict__ bm,
    const float* __restrict__ Wr, const float* __restrict__ br,
    const float* __restrict__ Wre, const float* __restrict__ bre,
    const float* __restrict__ Wim, const float* __restrict__ bim,
    const float* __restrict__ Wc,  const float* __restrict__ bc)
{
    __shared__ float in_m[8][64];
    __shared__ float in_r[8][128];
    __shared__ float in_re[8][128];
    __shared__ float in_im[8][128];
    __shared__ float comb[768 * 8];       // [k][r] layout, 24 KB

    const int tid = threadIdx.x;
    const int r0  = blockIdx.x * 8;

    for (int i = tid; i < 8 * 64; i += 256)
        in_m[i >> 6][i & 63] = motion[(r0 + (i >> 6)) * 64 + (i & 63)];
    for (int i = tid; i < 8 * 128; i += 256) {
        const int r = i >> 7, k = i & 127;
        in_r[r][k]  = robot[(r0 + r) * 128 + k];
        in_re[r][k] = (k < 64) ? osr[(r0 + r) * 64 + k] : orr_[(r0 + r) * 64 + k - 64];
        in_im[r][k] = (k < 64) ? osi[(r0 + r) * 64 + k] : ori_[(r0 + r) * 64 + k - 64];
    }
    __syncthreads();

    const int n = tid;
    float a[8];

    // ms
    #pragma unroll
    for (int r = 0; r < 8; r++) a[r] = bm[n];
    #pragma unroll 4
    for (int k = 0; k < 64; k++) {
        const float wv = Wm[k * 256 + n];
        #pragma unroll
        for (int r = 0; r < 8; r++) a[r] = fmaf(in_m[r][k], wv, a[r]);
    }
    #pragma unroll
    for (int r = 0; r < 8; r++) comb[n * 8 + r] = fmaxf(a[r], 0.f);

    // rs
    #pragma unroll
    for (int r = 0; r < 8; r++) a[r] = br[n];
    #pragma unroll 4
    for (int k = 0; k < 128; k++) {
        const float wv = Wr[k * 256 + n];
        #pragma unroll
        for (int r = 0; r < 8; r++) a[r] = fmaf(in_r[r][k], wv, a[r]);
    }
    #pragma unroll
    for (int r = 0; r < 8; r++) comb[(256 + n) * 8 + r] = fmaxf(a[r], 0.f);

    // re / im
    if (n < 128) {
        #pragma unroll
        for (int r = 0; r < 8; r++) a[r] = bre[n];
        #pragma unroll 4
        for (int k = 0; k < 128; k++) {
            const float wv = Wre[k * 128 + n];
            #pragma unroll
            for (int r = 0; r < 8; r++) a[r] = fmaf(in_re[r][k], wv, a[r]);
        }
        #pragma unroll
        for (int r = 0; r < 8; r++) comb[(512 + n) * 8 + r] = fmaxf(a[r], 0.f);
    } else {
        const int m = n - 128;
        #pragma unroll
        for (int r = 0; r < 8; r++) a[r] = bim[m];
        #pragma unroll 4
        for (int k = 0; k < 128; k++) {
            const float wv = Wim[k * 128 + m];
            #pragma unroll
            for (int r = 0; r < 8; r++) a[r] = fmaf(in_im[r][k], wv, a[r]);
        }
        #pragma unroll
        for (int r = 0; r < 8; r++) comb[(640 + m) * 8 + r] = fmaxf(a[r], 0.f);
    }
    __syncthreads();

    // combine: FFMA2 over row pairs
    unsigned long long s2[4];
    {
        const unsigned long long b2 = dup2(bc[n]);
        #pragma unroll
        for (int h = 0; h < 4; h++) s2[h] = b2;
    }
    #pragma unroll 4
    for (int k = 0; k < 768; k++) {
        const unsigned long long wv = dup2(Wc[k * 256 + n]);
        const float4 c03 = *(const float4*)&comb[k * 8];
        const float4 c47 = *(const float4*)&comb[k * 8 + 4];
        F2U p0, p1, p2, p3;
        p0.f = make_float2(c03.x, c03.y);
        p1.f = make_float2(c03.z, c03.w);
        p2.f = make_float2(c47.x, c47.y);
        p3.f = make_float2(c47.z, c47.w);
        fma2(s2[0], wv, p0.u);
        fma2(s2[1], wv, p1.u);
        fma2(s2[2], wv, p2.u);
        fma2(s2[3], wv, p3.u);
    }
    #pragma unroll
    for (int h = 0; h < 4; h++) {
        F2U e; e.u = s2[h];
        g_state[(r0 + 2*h)     * 256 + n] = fmaxf(e.f.x, 0.f);
        g_state[(r0 + 2*h + 1) * 256 + n] = fmaxf(e.f.y, 0.f);
    }
}

// ---------------------------------------------------------------------------
// xwk body (producer): unchanged from R16.
// ---------------------------------------------------------------------------
__device__ __forceinline__ void xwk_body(
    char* smem, int bid,
    const float* __restrict__ hist, const float* __restrict__ act,
    const float* __restrict__ bl)
{
    __half (*A_s)[72] = (__half(*)[72])smem;
    __half (*B_s)[72] = (__half(*)[72])(smem + 128 * 72 * 2);

    const int tid  = threadIdx.x;
    const int lane = tid & 31;
    const int wid  = tid >> 5;
    const int wm   = wid >> 2;
    const int wn   = wid & 3;
    const int bx   = bid & 7;
    const int by   = bid >> 3;
    const int bn0  = bx * 128;
    const int bm0  = by * 128;

    float acc[2][4][4];
    #pragma unroll
    for (int i = 0; i < 2; i++)
        #pragma unroll
        for (int j = 0; j < 4; j++)
            #pragma unroll
            for (int q = 0; q < 4; q++) acc[i][j][q] = 0.f;

    for (int kc = 0; kc < 256; kc += 64) {
        #pragma unroll
        for (int it = 0; it < 2; it++) {
            const int slot = it * 512 + tid;
            const int row  = slot >> 3;
            const int k8   = (slot & 7) * 8;
            const int m    = bm0 + row;
            const int t    = m >> 9, b = m & 511;
            const float* src = (t < 127)
                ? (hist + ((size_t)b * STEPS + t) * DIN + kc + k8)
                : (act  + ((size_t)b * STEPS + (t - 127)) * DIN + kc + k8);
            float4 f0 = *(const float4*)src;
            float4 f1 = *(const float4*)(src + 4);
            uint4 v;
            v.x = pack_h2(f0.x, f0.y); v.y = pack_h2(f0.z, f0.w);
            v.z = pack_h2(f1.x, f1.y); v.w = pack_h2(f1.z, f1.w);
            *(uint4*)&A_s[row][k8] = v;
        }
        #pragma unroll
        for (int it = 0; it < 2; it++) {
            const int slot = it * 512 + tid;
            const int n    = slot >> 3;
            const int k8   = (slot & 7) * 8;
            *(uint4*)&B_s[n][k8] =
                *(const uint4*)(g_WkT + (size_t)(bn0 + n) * 256 + kc + k8);
        }
        __syncthreads();

        #pragma unroll
        for (int ks = 0; ks < 4; ks++) {
            const int kb = ks * 16 + ((lane >> 4) << 3);
            uint32_t af[2][4];
            #pragma unroll
            for (int im = 0; im < 2; im++)
                ldsm4(af[im][0], af[im][1], af[im][2], af[im][3],
                      smem_u32(&A_s[wm*32 + im*16 + (lane & 15)][kb]));
            uint32_t bq[2][4];
            #pragma unroll
            for (int g2 = 0; g2 < 2; g2++)
                ldsm4(bq[g2][0], bq[g2][1], bq[g2][2], bq[g2][3],
                      smem_u32(&B_s[wn*32 + g2*16 + (lane & 15)][kb]));
            #pragma unroll
            for (int im = 0; im < 2; im++)
                #pragma unroll
                for (int g2 = 0; g2 < 2; g2++) {
                    mma16816(acc[im][g2*2],     af[im], bq[g2][0], bq[g2][2]);
                    mma16816(acc[im][g2*2 + 1], af[im], bq[g2][1], bq[g2][3]);
                }
        }
        __syncthreads();
    }

    const int r  = lane >> 2;
    const int c2 = (lane & 3) * 2;
    #pragma unroll
    for (int im = 0; im < 2; im++) {
        #pragma unroll
        for (int nt = 0; nt < 4; nt++) {
            const int gm  = bm0 + wm*32 + im*16 + r;
            const int gnO = bn0 + wn*32 + nt*8 + c2;
            const int f   = gnO & 255, g = gnO >> 8;
            const int nc  = ((f >> 4) << 6) + (g << 4) + (f & 15);
            const float b0 = bl[gnO], b1 = bl[gnO + 1];
            *(float2*)(g_G + (size_t)gm * G4 + nc) =
                make_float2(acc[im][nt][0] + b0, acc[im][nt][1] + b1);
            *(float2*)(g_G + (size_t)(gm + 8) * G4 + nc) =
                make_float2(acc[im][nt][2] + b0, acc[im][nt][3] + b1);
        }
    }

    __threadfence();
    __syncthreads();
    if (tid == 0) atomicAdd(&g_cnt[by], 1);
}

// ---------------------------------------------------------------------------
// recur body v2: pairwise feature-split. CTA pair p = {2p, 2p+1} owns rows
// [16p,16p+16); each CTA computes 512 permuted gate-cols (8 feature groups).
// Warp u: w_loc = u>>1, j = u&1, wg = half*8 + w_loc; handles all 4 gates of
// features 16*wg + 8j + [0,8). h halves exchanged per step via g_hx (fp16,
// L2) + monotonic per-CTA flags. mma/CTA/step: 1024 (half of R16).
// ---------------------------------------------------------------------------
__device__ __forceinline__ void recur_body(char* smem)
{
    __half* h_s = (__half*)smem;          // [16][HS_STRIDE]

    const int tid  = threadIdx.x;
    const int lane = tid & 31;
    const int u    = tid >> 5;            // warp 0..15
    const int bid  = blockIdx.x;
    const int p    = bid >> 1;            // pair id 0..31
    const int half = bid & 1;
    const int peer = bid ^ 1;
    const int r0   = p * 16;
    const int wloc = u >> 1;
    const int j    = u & 1;
    const int wg   = half * 8 + wloc;     // feature group 0..15
    const int zr   = lane >> 2;
    const int zc   = (lane & 3) * 2;
    const int yb   = p >> 3;
    const int f0   = 16 * wg + 8 * j + zc;

    // full h(0) into smem
    {
        const int row = tid >> 5;         // 0..15
        const int f   = (tid & 31) * 8;
        const float* sp = g_state + (size_t)(r0 + row) * 256 + f;
        uint4 v;
        v.x = pack_h2(sp[0], sp[1]); v.y = pack_h2(sp[2], sp[3]);
        v.z = pack_h2(sp[4], sp[5]); v.w = pack_h2(sp[6], sp[7]);
        *(uint4*)&h_s[row * HS_STRIDE + f] = v;
    }
    float c[4];
    c[0] = g_state[(size_t)(r0 + zr) * 256 + f0];
    c[1] = g_state[(size_t)(r0 + zr) * 256 + f0 + 1];
    c[2] = g_state[(size_t)(r0 + zr + 8) * 256 + f0];
    c[3] = g_state[(size_t)(r0 + zr + 8) * 256 + f0 + 1];

    if (tid == 0) {
        while (*(volatile int*)&g_cnt[yb] < YTARGET) __nanosleep(128);
    }
    __syncthreads();

    const uint4* bbase = g_WrkF + lane;
    float h[4];

    #pragma unroll 1
    for (int t = 0; t < TSTEPS; t++) {
        // G prefetch (lands under MMA)
        const float* Gb = g_G + ((size_t)t * BATCH + r0) * G4;
        float2 ga[4][2];
        #pragma unroll
        for (int g = 0; g < 4; g++) {
            const int nc = 64 * wg + (2 * g + j) * 8 + zc;
            ga[g][0] = __ldcg((const float2*)(Gb + (size_t)zr * G4 + nc));
            ga[g][1] = __ldcg((const float2*)(Gb + (size_t)(zr + 8) * G4 + nc));
        }

        float acc[4][4];
        #pragma unroll
        for (int g = 0; g < 4; g++)
            #pragma unroll
            for (int q = 0; q < 4; q++) acc[g][q] = 0.f;

        uint4 bf[4];
        #pragma unroll
        for (int g = 0; g < 4; g++)
            bf[g] = bbase[((wg * 8 + 2 * g + j) * 8) * 32];

        #pragma unroll
        for (int kp = 0; kp < 8; kp++) {
            uint4 bc[4];
            #pragma unroll
            for (int g = 0; g < 4; g++) bc[g] = bf[g];
            if (kp < 7) {
                #pragma unroll
                for (int g = 0; g < 4; g++)
                    bf[g] = bbase[((wg * 8 + 2 * g + j) * 8 + kp + 1) * 32];
            }
            const int kb = kp * 32 + ((lane >> 4) << 3);
            uint32_t a0[4], a1[4];
            ldsm4(a0[0], a0[1], a0[2], a0[3],
                  smem_u32(&h_s[(lane & 15) * HS_STRIDE + kb]));
            ldsm4(a1[0], a1[1], a1[2], a1[3],
                  smem_u32(&h_s[(lane & 15) * HS_STRIDE + kb + 16]));
            #pragma unroll
            for (int g = 0; g < 4; g++) {
                mma16816(acc[g], a0, bc[g].x, bc[g].y);
                mma16816(acc[g], a1, bc[g].z, bc[g].w);
            }
        }
        __syncthreads();   // all h_s reads done

        // gates in fragment registers
        #pragma unroll
        for (int q = 0; q < 4; q++) {
            const int rh = q >> 1;
            const float gi = (q & 1) ? ga[0][rh].y : ga[0][rh].x;
            const float gf = (q & 1) ? ga[1][rh].y : ga[1][rh].x;
            const float gg = (q & 1) ? ga[2][rh].y : ga[2][rh].x;
            const float go = (q & 1) ? ga[3][rh].y : ga[3][rh].x;
            const float zi = acc[0][q] + gi;
            const float zf = acc[1][q] + gf;
            const float zg = acc[2][q] + gg;
            const float zo = acc[3][q] + go;
            c[q] = sigm(zf) * c[q] + sigm(zi) * tanha(zg);
            h[q] = sigm(zo) * tanha(c[q]);
        }

        // write own half: smem + exchange buffer
        const uint32_t hv0 = pack_h2(h[0], h[1]);
        const uint32_t hv1 = pack_h2(h[2], h[3]);
        *(uint32_t*)&h_s[zr       * HS_STRIDE + f0] = hv0;
        *(uint32_t*)&h_s[(zr + 8) * HS_STRIDE + f0] = hv1;

        if (t + 1 < TSTEPS) {
            *(uint32_t*)&g_hx[(size_t)(r0 + zr) * 256 + f0]     = hv0;
            *(uint32_t*)&g_hx[(size_t)(r0 + zr + 8) * 256 + f0] = hv1;
            __threadfence();
            __syncthreads();
            if (tid == 0) {
                atomicAdd(&g_hf[bid], 1);
                while (*(volatile int*)&g_hf[peer] <= t) __nanosleep(64);
                const int y = 4 * (t + 1) + yb;
                while (*(volatile int*)&g_cnt[y] < YTARGET) __nanosleep(64);
            }
            __syncthreads();
            // read peer half into h_s
            {
                const int row = tid >> 5;
                const int fp  = (1 - half) * 128 + (tid & 31) * 4;
                const uint2 v = __ldcg((const uint2*)&g_hx[(size_t)(r0 + row) * 256 + fp]);
                *(uint2*)&h_s[row * HS_STRIDE + fp] = v;
            }
            __syncthreads();
        }
    }

    // final h -> g_h (own half only; peer writes the other)
    *(float2*)(g_h + (size_t)(r0 + zr) * 256 + f0)     = make_float2(h[0], h[1]);
    *(float2*)(g_h + (size_t)(r0 + zr + 8) * 256 + f0) = make_float2(h[2], h[3]);
}

// ---------------------------------------------------------------------------
// K2: fused producer/consumer kernel. bid 0..63 = recur, 64.. = xwk.
// ---------------------------------------------------------------------------
__global__ void __launch_bounds__(512, 1) fused_kernel(
    const float* __restrict__ hist, const float* __restrict__ act,
    const float* __restrict__ bl)
{
    extern __shared__ char smem[];
    if (blockIdx.x < NRECUR) recur_body(smem);
    else                     xwk_body(smem, blockIdx.x - NRECUR, hist, act, bl);
}

// ---------------------------------------------------------------------------
// K4: out = relu(h @ Wo + bo), [512,1]. One warp per batch row.
// ---------------------------------------------------------------------------
__global__ void out_kernel(const float* __restrict__ Wo,
                           const float* __restrict__ bo,
                           float* __restrict__ out)
{
    const int b = blockIdx.x;
    const int lane = threadIdx.x;
    float s = 0.f;
    #pragma unroll
    for (int k = lane; k < 256; k += 32) s += g_h[b*256 + k] * Wo[k];
    #pragma unroll
    for (int off = 16; off; off >>= 1) s += __shfl_down_sync(0xffffffffu, s, off);
    if (lane == 0) out[b] = fmaxf(s + bo[0], 0.f);
}

// ---------------------------------------------------------------------------
extern "C" void kernel_launch(void* const* d_in, const int* in_sizes, int n_in,
                              void* d_out, int out_size)
{
    const float* motion = (const float*)d_in[0];
    const float* robot  = (const float*)d_in[1];
    const float* osr    = (const float*)d_in[2];
    const float* osi    = (const float*)d_in[3];
    const float* hist   = (const float*)d_in[4];
    const float* act    = (const float*)d_in[5];
    const float* orr_   = (const float*)d_in[6];
    const float* ori_   = (const float*)d_in[7];
    const float* Wm  = (const float*)d_in[8];
    const float* bm  = (const float*)d_in[9];
    const float* Wr  = (const float*)d_in[10];
    const float* br  = (const float*)d_in[11];
    const float* Wre = (const float*)d_in[12];
    const float* bre = (const float*)d_in[13];
    const float* Wim = (const float*)d_in[14];
    const float* bim = (const float*)d_in[15];
    const float* Wc  = (const float*)d_in[16];
    const float* bc  = (const float*)d_in[17];
    const float* Wk  = (const float*)d_in[18];
    const float* Wrk = (const float*)d_in[19];
    const float* bl  = (const float*)d_in[20];
    const float* Wo  = (const float*)d_in[21];
    const float* bo  = (const float*)d_in[22];
    float* out = (float*)d_out;

    static int smem_set = 0;
    if (!smem_set) {
        cudaFuncSetAttribute(fused_kernel,
                             cudaFuncAttributeMaxDynamicSharedMemorySize, FUSED_SMEM);
        smem_set = 1;
    }

    init_cnt<<<(NYB + 255) / 256, 256>>>();
    reformat_wrkF<<<128, 256>>>(Wrk);
    reformat_wk<<<1024, 256>>>(Wk);

    preamble_kernel<<<BATCH / 8, 256>>>(motion, robot, osr, osi, orr_, ori_,
                                        Wm, bm, Wr, br, Wre, bre, Wim, bim, Wc, bc);

    fused_kernel<<<NRECUR + NXWK, 512, FUSED_SMEM>>>(hist, act, bl);

    out_kernel<<<BATCH, 32>>>(Wo, bo, out);
}